// round 1
// baseline (speedup 1.0000x reference)
#include <cuda_runtime.h>
#include <cstdint>

// Problem constants
constexpr int Bb = 2;
constexpr int Tt = 2048;
constexpr int Cc = 1024;
constexpr int Hh = 16;
constexpr int Dd = 64;
constexpr int Mrows = Bb * Tt;        // 4096
constexpr int N3C = 3 * Cc;           // 3072

// Scratch (static device memory; no allocations allowed)
__device__ float g_qkv[Mrows * N3C];          // [B*T, 3C]
__device__ float g_q[Bb * Hh * Tt * Dd];      // [B,H,T,D]
__device__ float g_k[Bb * Hh * Tt * Dd];
__device__ float g_v[Bb * Hh * Tt * Dd];
__device__ float g_y[Mrows * Cc];             // [B,T,C] attention output
__device__ float g_cos[Tt * (Dd / 2)];        // [T, 32]
__device__ float g_sin[Tt * (Dd / 2)];

// ---------------------------------------------------------------------------
// RoPE table: cos/sin per (t, pair)
// ---------------------------------------------------------------------------
__global__ void rope_table_kernel() {
    int idx = blockIdx.x * blockDim.x + threadIdx.x;
    if (idx >= Tt * (Dd / 2)) return;
    int t = idx / (Dd / 2);
    int i = idx % (Dd / 2);
    // inv_freq = 10000^{-(2i)/D}
    double inv = exp(-((double)(2 * i) / (double)Dd) * log(10000.0));
    float ang = (float)((double)t * inv);
    g_cos[idx] = cosf(ang);
    g_sin[idx] = sinf(ang);
}

// ---------------------------------------------------------------------------
// SGEMM: C = A[MxK] @ B[KxN] + bias[N]
// BM=BN=128, BK=8, 256 threads, 8x8 microtile per thread.
// M, N, K all divide tile sizes for our shapes.
// ---------------------------------------------------------------------------
__global__ __launch_bounds__(256) void sgemm_bias_kernel(
    const float* __restrict__ A, const float* __restrict__ Bw,
    const float* __restrict__ bias, float* __restrict__ Cout,
    int M, int N, int K)
{
    __shared__ float As[8][132];   // padded to avoid store conflicts
    __shared__ float Bs[8][128];

    const int tid = threadIdx.x;
    const int mBase = blockIdx.y * 128;
    const int nBase = blockIdx.x * 128;
    const int tx = tid & 15;        // 0..15  (n dir)
    const int ty = tid >> 4;        // 0..15  (m dir)

    float acc[8][8] = {};

    // A tile loader mapping: 128 rows x 8 cols = 256 float4
    const int arow = tid >> 1;            // 0..127
    const int acol = (tid & 1) * 4;       // 0 or 4
    // B tile loader mapping: 8 rows x 128 cols = 256 float4
    const int brow = tid >> 5;            // 0..7
    const int bcol = (tid & 31) * 4;      // 0..124

    const float* Aptr = A + (size_t)(mBase + arow) * K + acol;
    const float* Bptr = Bw + (size_t)brow * N + nBase + bcol;

    for (int kk = 0; kk < K; kk += 8) {
        float4 av = *(const float4*)(Aptr + kk);
        float4 bv = *(const float4*)(Bptr + (size_t)kk * N);
        As[acol + 0][arow] = av.x;
        As[acol + 1][arow] = av.y;
        As[acol + 2][arow] = av.z;
        As[acol + 3][arow] = av.w;
        *(float4*)&Bs[brow][bcol] = bv;
        __syncthreads();

#pragma unroll
        for (int k = 0; k < 8; k++) {
            float a[8], b[8];
            *(float4*)&a[0] = *(const float4*)&As[k][ty * 8];
            *(float4*)&a[4] = *(const float4*)&As[k][ty * 8 + 4];
            *(float4*)&b[0] = *(const float4*)&Bs[k][tx * 8];
            *(float4*)&b[4] = *(const float4*)&Bs[k][tx * 8 + 4];
#pragma unroll
            for (int i = 0; i < 8; i++)
#pragma unroll
                for (int j = 0; j < 8; j++)
                    acc[i][j] += a[i] * b[j];
        }
        __syncthreads();
    }

    // bias
    float bb[8];
#pragma unroll
    for (int j = 0; j < 8; j++) bb[j] = bias[nBase + tx * 8 + j];

#pragma unroll
    for (int i = 0; i < 8; i++) {
        int row = mBase + ty * 8 + i;
        float* cp = Cout + (size_t)row * N + nBase + tx * 8;
        float4 v0, v1;
        v0.x = acc[i][0] + bb[0]; v0.y = acc[i][1] + bb[1];
        v0.z = acc[i][2] + bb[2]; v0.w = acc[i][3] + bb[3];
        v1.x = acc[i][4] + bb[4]; v1.y = acc[i][5] + bb[5];
        v1.z = acc[i][6] + bb[6]; v1.w = acc[i][7] + bb[7];
        ((float4*)cp)[0] = v0;
        ((float4*)cp)[1] = v1;
    }
}

// ---------------------------------------------------------------------------
// Transform: qkv[B*T, 3C] -> Q/K/V [B,H,T,D] with RoPE on Q,K
// One thread per (row, even-column pair)
// ---------------------------------------------------------------------------
__global__ void transform_kernel() {
    int idx = blockIdx.x * blockDim.x + threadIdx.x;
    const int pairsPerRow = N3C / 2;  // 1536
    if (idx >= Mrows * pairsPerRow) return;
    int m = idx / pairsPerRow;
    int cp = idx % pairsPerRow;
    int c = cp * 2;

    int b = m / Tt;
    int t = m % Tt;
    int part = c / Cc;            // 0=q 1=k 2=v
    int w = c % Cc;
    int h = w / Dd;
    int d = w % Dd;

    float a0 = g_qkv[(size_t)m * N3C + c];
    float a1 = g_qkv[(size_t)m * N3C + c + 1];

    float o0 = a0, o1 = a1;
    if (part < 2) {
        int i = d / 2;
        float co = g_cos[t * (Dd / 2) + i];
        float si = g_sin[t * (Dd / 2) + i];
        o0 = a0 * co - a1 * si;
        o1 = a1 * co + a0 * si;
    }
    float* dst = (part == 0) ? g_q : (part == 1) ? g_k : g_v;
    size_t off = (((size_t)(b * Hh + h)) * Tt + t) * Dd + d;
    dst[off] = o0;
    dst[off + 1] = o1;
}

// ---------------------------------------------------------------------------
// Flash attention (causal): 1 thread = 1 query row; 128 queries per CTA;
// 32-key tiles staged in smem. Q/O in registers.
// ---------------------------------------------------------------------------
__global__ __launch_bounds__(128) void flash_attn_kernel(
    const float* __restrict__ Q, const float* __restrict__ K,
    const float* __restrict__ V, float* __restrict__ Y)
{
    __shared__ float Ks[32][64];
    __shared__ float Vs[32][64];

    const int bh = blockIdx.y;                 // b*H + h
    const int m0 = blockIdx.x * 128;
    const int tidx = threadIdx.x;
    const int qi = m0 + tidx;

    const float* qptr = Q + ((size_t)bh * Tt + qi) * Dd;
    float4 q4[16];
#pragma unroll
    for (int i = 0; i < 16; i++) {
        q4[i] = ((const float4*)qptr)[i];
        q4[i].x *= 0.125f; q4[i].y *= 0.125f;
        q4[i].z *= 0.125f; q4[i].w *= 0.125f;
    }

    float4 o4[16];
#pragma unroll
    for (int i = 0; i < 16; i++) { o4[i].x = 0.f; o4[i].y = 0.f; o4[i].z = 0.f; o4[i].w = 0.f; }
    float mrun = -1e30f;
    float l = 0.f;

    const float* Kb = K + (size_t)bh * Tt * Dd;
    const float* Vb = V + (size_t)bh * Tt * Dd;
    const int jend = m0 + 128;

    for (int j0 = 0; j0 < jend; j0 += 32) {
        // cooperative load of K/V tiles (32x64 = 512 float4 each)
        const float4* kg = (const float4*)(Kb + (size_t)j0 * Dd);
        const float4* vg = (const float4*)(Vb + (size_t)j0 * Dd);
        float4* ks = (float4*)Ks;
        float4* vs = (float4*)Vs;
#pragma unroll
        for (int u = 0; u < 4; u++) {
            ks[u * 128 + tidx] = kg[u * 128 + tidx];
            vs[u * 128 + tidx] = vg[u * 128 + tidx];
        }
        __syncthreads();

        float s[32];
        const int jmaxr = qi - j0;   // r <= jmaxr is valid
#pragma unroll
        for (int r = 0; r < 32; r++) {
            const float4* kr = (const float4*)&Ks[r][0];
            float acc = 0.f;
#pragma unroll
            for (int d = 0; d < 16; d++) {
                float4 kv = kr[d];
                acc += q4[d].x * kv.x + q4[d].y * kv.y + q4[d].z * kv.z + q4[d].w * kv.w;
            }
            s[r] = (r <= jmaxr) ? acc : -1e30f;
        }

        float tmax = s[0];
#pragma unroll
        for (int r = 1; r < 32; r++) tmax = fmaxf(tmax, s[r]);
        float mnew = fmaxf(mrun, tmax);
        float corr = __expf(mrun - mnew);
        mrun = mnew;
        l *= corr;
#pragma unroll
        for (int d = 0; d < 16; d++) {
            o4[d].x *= corr; o4[d].y *= corr; o4[d].z *= corr; o4[d].w *= corr;
        }

#pragma unroll
        for (int r = 0; r < 32; r++) {
            float p = __expf(s[r] - mnew);
            l += p;
            const float4* vr = (const float4*)&Vs[r][0];
#pragma unroll
            for (int d = 0; d < 16; d++) {
                float4 vv = vr[d];
                o4[d].x += p * vv.x; o4[d].y += p * vv.y;
                o4[d].z += p * vv.z; o4[d].w += p * vv.w;
            }
        }
        __syncthreads();
    }

    const float inv = 1.f / l;
    const int b = bh >> 4;
    const int h = bh & 15;
    float* yp = Y + ((size_t)(b * Tt + qi)) * Cc + h * Dd;
#pragma unroll
    for (int d = 0; d < 16; d++) {
        float4 ov = o4[d];
        ov.x *= inv; ov.y *= inv; ov.z *= inv; ov.w *= inv;
        ((float4*)yp)[d] = ov;
    }
}

// ---------------------------------------------------------------------------
// launch
// ---------------------------------------------------------------------------
extern "C" void kernel_launch(void* const* d_in, const int* in_sizes, int n_in,
                              void* d_out, int out_size) {
    const float* x      = (const float*)d_in[0];   // [B,T,C]
    const float* w_attn = (const float*)d_in[1];   // [C,3C]
    const float* b_attn = (const float*)d_in[2];   // [3C]
    const float* w_proj = (const float*)d_in[3];   // [C,C]
    const float* b_proj = (const float*)d_in[4];   // [C]
    float* out = (float*)d_out;                    // [B,T,C]

    float *qkv, *q, *k, *v, *y;
    cudaGetSymbolAddress((void**)&qkv, g_qkv);
    cudaGetSymbolAddress((void**)&q, g_q);
    cudaGetSymbolAddress((void**)&k, g_k);
    cudaGetSymbolAddress((void**)&v, g_v);
    cudaGetSymbolAddress((void**)&y, g_y);

    // 1. RoPE table
    {
        int total = Tt * (Dd / 2);
        rope_table_kernel<<<(total + 255) / 256, 256>>>();
    }
    // 2. QKV GEMM: [4096,1024] @ [1024,3072] + bias
    {
        dim3 grid(N3C / 128, Mrows / 128);
        sgemm_bias_kernel<<<grid, 256>>>(x, w_attn, b_attn, qkv, Mrows, N3C, Cc);
    }
    // 3. RoPE + scatter into Q/K/V [B,H,T,D]
    {
        int total = Mrows * (N3C / 2);
        transform_kernel<<<(total + 255) / 256, 256>>>();
    }
    // 4. Flash attention -> y [B,T,C]
    {
        dim3 grid(Tt / 128, Bb * Hh);
        flash_attn_kernel<<<grid, 128>>>(q, k, v, y);
    }
    // 5. Output projection: [4096,1024] @ [1024,1024] + bias
    {
        dim3 grid(Cc / 128, Mrows / 128);
        sgemm_bias_kernel<<<grid, 256>>>(y, w_proj, b_proj, out, Mrows, Cc, Cc);
    }
}

// round 3
// speedup vs baseline: 1.3672x; 1.3672x over previous
#include <cuda_runtime.h>
#include <cstdint>

// Problem constants
constexpr int Bb = 2;
constexpr int Tt = 2048;
constexpr int Cc = 1024;
constexpr int Hh = 16;
constexpr int Dd = 64;
constexpr int Mrows = Bb * Tt;        // 4096
constexpr int N3C = 3 * Cc;           // 3072

// Scratch (static device memory)
__device__ float g_q[Bb * Hh * Tt * Dd];
__device__ float g_k[Bb * Hh * Tt * Dd];
__device__ float g_v[Bb * Hh * Tt * Dd];
__device__ float g_y[Mrows * Cc];
__device__ float g_cos[Tt * (Dd / 2)];
__device__ float g_sin[Tt * (Dd / 2)];

__device__ __forceinline__ uint32_t f2tf32(float x) {
    uint32_t r; asm("cvt.rna.tf32.f32 %0, %1;" : "=r"(r) : "f"(x)); return r;
}

__device__ __forceinline__ void mma_tf32(float* c, const uint32_t* a, const uint32_t* b) {
    asm volatile(
        "mma.sync.aligned.m16n8k8.row.col.f32.tf32.tf32.f32 "
        "{%0,%1,%2,%3}, {%4,%5,%6,%7}, {%8,%9}, {%0,%1,%2,%3};"
        : "+f"(c[0]), "+f"(c[1]), "+f"(c[2]), "+f"(c[3])
        : "r"(a[0]), "r"(a[1]), "r"(a[2]), "r"(a[3]), "r"(b[0]), "r"(b[1]));
}

// ---------------------------------------------------------------------------
// RoPE table
// ---------------------------------------------------------------------------
__global__ void rope_table_kernel() {
    int idx = blockIdx.x * blockDim.x + threadIdx.x;
    if (idx >= Tt * (Dd / 2)) return;
    int t = idx / (Dd / 2);
    int i = idx % (Dd / 2);
    double inv = exp(-((double)(2 * i) / (double)Dd) * log(10000.0));
    float ang = (float)((double)t * inv);
    g_cos[idx] = cosf(ang);
    g_sin[idx] = sinf(ang);
}

// ---------------------------------------------------------------------------
// TF32 mma.sync GEMM: out[M,N] = A[M,K] @ Bw[K,N] + bias[N]
// CTA tile 128x128, BK=32, 256 threads = 8 warps (2m x 4n), warp tile 64x32.
// mode 0: plain write. mode 1: QKV epilogue (bias + RoPE + head scatter).
// ---------------------------------------------------------------------------
constexpr int APAD = 36;    // floats per A smem row (32 + 4)
constexpr int BPAD = 136;   // floats per B smem row (128 + 8)

__global__ __launch_bounds__(256) void mma_gemm_kernel(
    const float* __restrict__ A, const float* __restrict__ Bw,
    const float* __restrict__ bias, float* __restrict__ out,
    int M, int N, int K, int mode)
{
    __shared__ float As[128 * APAD];
    __shared__ float Bs[32 * BPAD];

    const int tid = threadIdx.x;
    const int lane = tid & 31;
    const int wid = tid >> 5;
    const int wm = wid >> 2;        // 0..1
    const int wn = wid & 3;         // 0..3
    const int mBase = blockIdx.y * 128;
    const int nBase = blockIdx.x * 128;

    const int g4 = lane >> 2;       // 0..7
    const int c4 = lane & 3;        // 0..3

    float acc[4][4][4] = {};

    // loader indices
    const int arow = tid >> 1;              // wrong granularity; recompute below
    (void)arow;

    float4 aS[4], bS[4];

    auto load_tiles = [&](int it) {
        const int k0 = it * 32;
#pragma unroll
        for (int p = 0; p < 4; p++) {
            int v = p * 256 + tid;
            int ar = v >> 3, ac = (v & 7) * 4;            // 128 rows x 8 float4
            aS[p] = *(const float4*)(A + (size_t)(mBase + ar) * K + k0 + ac);
            int br = v >> 5, bc = (v & 31) * 4;           // 32 rows x 32 float4
            bS[p] = *(const float4*)(Bw + (size_t)(k0 + br) * N + nBase + bc);
        }
    };
    auto store_tiles = [&]() {
#pragma unroll
        for (int p = 0; p < 4; p++) {
            int v = p * 256 + tid;
            int ar = v >> 3, ac = (v & 7) * 4;
            uint32_t* ad = (uint32_t*)&As[ar * APAD + ac];
            ad[0] = f2tf32(aS[p].x); ad[1] = f2tf32(aS[p].y);
            ad[2] = f2tf32(aS[p].z); ad[3] = f2tf32(aS[p].w);
            int br = v >> 5, bc = (v & 31) * 4;
            uint32_t* bd = (uint32_t*)&Bs[br * BPAD + bc];
            bd[0] = f2tf32(bS[p].x); bd[1] = f2tf32(bS[p].y);
            bd[2] = f2tf32(bS[p].z); bd[3] = f2tf32(bS[p].w);
        }
    };

    const uint32_t* As32 = (const uint32_t*)As;
    const uint32_t* Bs32 = (const uint32_t*)Bs;
    const int KT = K / 32;

    load_tiles(0);
    for (int it = 0; it < KT; it++) {
        store_tiles();
        __syncthreads();
        if (it + 1 < KT) load_tiles(it + 1);   // prefetch overlaps compute

#pragma unroll
        for (int ks = 0; ks < 4; ks++) {
            const int kk = ks * 8;
            uint32_t af[4][4];
#pragma unroll
            for (int mt = 0; mt < 4; mt++) {
                int m = wm * 64 + mt * 16 + g4;
                af[mt][0] = As32[m * APAD + kk + c4];
                af[mt][1] = As32[(m + 8) * APAD + kk + c4];
                af[mt][2] = As32[m * APAD + kk + 4 + c4];
                af[mt][3] = As32[(m + 8) * APAD + kk + 4 + c4];
            }
            uint32_t bf[4][2];
#pragma unroll
            for (int nt = 0; nt < 4; nt++) {
                int n = wn * 32 + nt * 8 + g4;
                bf[nt][0] = Bs32[(kk + c4) * BPAD + n];
                bf[nt][1] = Bs32[(kk + 4 + c4) * BPAD + n];
            }
#pragma unroll
            for (int mt = 0; mt < 4; mt++)
#pragma unroll
                for (int nt = 0; nt < 4; nt++)
                    mma_tf32(acc[mt][nt], af[mt], bf[nt]);
        }
        __syncthreads();
    }

    // Epilogue
#pragma unroll
    for (int mt = 0; mt < 4; mt++) {
#pragma unroll
        for (int nt = 0; nt < 4; nt++) {
            const int col = nBase + wn * 32 + nt * 8 + 2 * c4;
            const float b0 = __ldg(&bias[col]);
            const float b1 = __ldg(&bias[col + 1]);
            const int row0 = mBase + wm * 64 + mt * 16 + g4;

            float v00 = acc[mt][nt][0] + b0, v01 = acc[mt][nt][1] + b1;
            float v10 = acc[mt][nt][2] + b0, v11 = acc[mt][nt][3] + b1;

            if (mode == 0) {
                *(float2*)(out + (size_t)row0 * N + col) = make_float2(v00, v01);
                *(float2*)(out + (size_t)(row0 + 8) * N + col) = make_float2(v10, v11);
            } else {
                const int part = col >> 10;          // 0=q 1=k 2=v
                const int h = (col & 1023) >> 6;
                const int d = col & 63;
                const int i = d >> 1;
                const int b = row0 >> 11;
                const int t0 = row0 & (Tt - 1);
                const int t1 = (row0 + 8) & (Tt - 1);
                if (part < 2) {
                    float co0 = g_cos[t0 * 32 + i], si0 = g_sin[t0 * 32 + i];
                    float co1 = g_cos[t1 * 32 + i], si1 = g_sin[t1 * 32 + i];
                    float r00 = v00 * co0 - v01 * si0;
                    float r01 = v01 * co0 + v00 * si0;
                    float r10 = v10 * co1 - v11 * si1;
                    float r11 = v11 * co1 + v10 * si1;
                    v00 = r00; v01 = r01; v10 = r10; v11 = r11;
                }
                float* dst = (part == 0) ? g_q : (part == 1) ? g_k : g_v;
                size_t base = ((size_t)(b * Hh + h)) * Tt;
                *(float2*)(dst + (base + t0) * Dd + d) = make_float2(v00, v01);
                *(float2*)(dst + (base + t1) * Dd + d) = make_float2(v10, v11);
            }
        }
    }
}

// ---------------------------------------------------------------------------
// Flash attention (causal), fp32 — unchanged (known good)
// ---------------------------------------------------------------------------
__global__ __launch_bounds__(128) void flash_attn_kernel(
    const float* __restrict__ Q, const float* __restrict__ K,
    const float* __restrict__ V, float* __restrict__ Y)
{
    __shared__ float Ks[32][64];
    __shared__ float Vs[32][64];

    const int bh = blockIdx.y;
    const int m0 = blockIdx.x * 128;
    const int tidx = threadIdx.x;
    const int qi = m0 + tidx;

    const float* qptr = Q + ((size_t)bh * Tt + qi) * Dd;
    float4 q4[16];
#pragma unroll
    for (int i = 0; i < 16; i++) {
        q4[i] = ((const float4*)qptr)[i];
        q4[i].x *= 0.125f; q4[i].y *= 0.125f;
        q4[i].z *= 0.125f; q4[i].w *= 0.125f;
    }

    float4 o4[16];
#pragma unroll
    for (int i = 0; i < 16; i++) { o4[i].x = 0.f; o4[i].y = 0.f; o4[i].z = 0.f; o4[i].w = 0.f; }
    float mrun = -1e30f;
    float l = 0.f;

    const float* Kb = K + (size_t)bh * Tt * Dd;
    const float* Vb = V + (size_t)bh * Tt * Dd;
    const int jend = m0 + 128;

    for (int j0 = 0; j0 < jend; j0 += 32) {
        const float4* kg = (const float4*)(Kb + (size_t)j0 * Dd);
        const float4* vg = (const float4*)(Vb + (size_t)j0 * Dd);
        float4* ks = (float4*)Ks;
        float4* vs = (float4*)Vs;
#pragma unroll
        for (int u = 0; u < 4; u++) {
            ks[u * 128 + tidx] = kg[u * 128 + tidx];
            vs[u * 128 + tidx] = vg[u * 128 + tidx];
        }
        __syncthreads();

        float s[32];
        const int jmaxr = qi - j0;
#pragma unroll
        for (int r = 0; r < 32; r++) {
            const float4* kr = (const float4*)&Ks[r][0];
            float acc = 0.f;
#pragma unroll
            for (int d = 0; d < 16; d++) {
                float4 kv = kr[d];
                acc += q4[d].x * kv.x + q4[d].y * kv.y + q4[d].z * kv.z + q4[d].w * kv.w;
            }
            s[r] = (r <= jmaxr) ? acc : -1e30f;
        }

        float tmax = s[0];
#pragma unroll
        for (int r = 1; r < 32; r++) tmax = fmaxf(tmax, s[r]);
        float mnew = fmaxf(mrun, tmax);
        float corr = __expf(mrun - mnew);
        mrun = mnew;
        l *= corr;
#pragma unroll
        for (int d = 0; d < 16; d++) {
            o4[d].x *= corr; o4[d].y *= corr; o4[d].z *= corr; o4[d].w *= corr;
        }

#pragma unroll
        for (int r = 0; r < 32; r++) {
            float p = __expf(s[r] - mnew);
            l += p;
            const float4* vr = (const float4*)&Vs[r][0];
#pragma unroll
            for (int d = 0; d < 16; d++) {
                float4 vv = vr[d];
                o4[d].x += p * vv.x; o4[d].y += p * vv.y;
                o4[d].z += p * vv.z; o4[d].w += p * vv.w;
            }
        }
        __syncthreads();
    }

    const float inv = 1.f / l;
    const int b = bh >> 4;
    const int h = bh & 15;
    float* yp = Y + ((size_t)(b * Tt + qi)) * Cc + h * Dd;
#pragma unroll
    for (int d = 0; d < 16; d++) {
        float4 ov = o4[d];
        ov.x *= inv; ov.y *= inv; ov.z *= inv; ov.w *= inv;
        ((float4*)yp)[d] = ov;
    }
}

// ---------------------------------------------------------------------------
// launch
// ---------------------------------------------------------------------------
extern "C" void kernel_launch(void* const* d_in, const int* in_sizes, int n_in,
                              void* d_out, int out_size) {
    const float* x      = (const float*)d_in[0];
    const float* w_attn = (const float*)d_in[1];   // [C, 3C]  (K-major: perfect for B)
    const float* b_attn = (const float*)d_in[2];
    const float* w_proj = (const float*)d_in[3];   // [C, C]
    const float* b_proj = (const float*)d_in[4];
    float* out = (float*)d_out;

    float *q, *k, *v, *y;
    cudaGetSymbolAddress((void**)&q, g_q);
    cudaGetSymbolAddress((void**)&k, g_k);
    cudaGetSymbolAddress((void**)&v, g_v);
    cudaGetSymbolAddress((void**)&y, g_y);

    // RoPE table
    {
        int total = Tt * (Dd / 2);
        rope_table_kernel<<<(total + 255) / 256, 256>>>();
    }
    // QKV GEMM (tf32 mma.sync) with fused bias + RoPE + head scatter
    mma_gemm_kernel<<<dim3(N3C / 128, Mrows / 128), 256>>>(
        x, w_attn, b_attn, nullptr, Mrows, N3C, Cc, 1);
    // Flash attention
    flash_attn_kernel<<<dim3(Tt / 128, Bb * Hh), 128>>>(q, k, v, y);
    // Output projection (tf32 mma.sync) with fused bias
    mma_gemm_kernel<<<dim3(Cc / 128, Mrows / 128), 256>>>(
        y, w_proj, b_proj, out, Mrows, Cc, Cc, 0);
}

// round 4
// speedup vs baseline: 4.0491x; 2.9616x over previous
#include <cuda_runtime.h>
#include <cstdint>

// Problem constants
constexpr int Bb = 2;
constexpr int Tt = 2048;
constexpr int Cc = 1024;
constexpr int Hh = 16;
constexpr int Dd = 64;
constexpr int Mrows = Bb * Tt;        // 4096
constexpr int N3C = 3 * Cc;           // 3072

// Scratch (static device memory)
__device__ float g_q[Bb * Hh * Tt * Dd];
__device__ float g_k[Bb * Hh * Tt * Dd];
__device__ float g_v[Bb * Hh * Tt * Dd];
__device__ float g_y[Mrows * Cc];
__device__ float g_cos[Tt * (Dd / 2)];
__device__ float g_sin[Tt * (Dd / 2)];

__device__ __forceinline__ uint32_t f2tf32(float x) {
    uint32_t r; asm("cvt.rna.tf32.f32 %0, %1;" : "=r"(r) : "f"(x)); return r;
}

__device__ __forceinline__ void mma_tf32(float* c, const uint32_t* a, const uint32_t* b) {
    asm volatile(
        "mma.sync.aligned.m16n8k8.row.col.f32.tf32.tf32.f32 "
        "{%0,%1,%2,%3}, {%4,%5,%6,%7}, {%8,%9}, {%0,%1,%2,%3};"
        : "+f"(c[0]), "+f"(c[1]), "+f"(c[2]), "+f"(c[3])
        : "r"(a[0]), "r"(a[1]), "r"(a[2]), "r"(a[3]), "r"(b[0]), "r"(b[1]));
}

// ---------------------------------------------------------------------------
// RoPE table
// ---------------------------------------------------------------------------
__global__ void rope_table_kernel() {
    int idx = blockIdx.x * blockDim.x + threadIdx.x;
    if (idx >= Tt * (Dd / 2)) return;
    int t = idx / (Dd / 2);
    int i = idx % (Dd / 2);
    double inv = exp(-((double)(2 * i) / (double)Dd) * log(10000.0));
    float ang = (float)((double)t * inv);
    g_cos[idx] = cosf(ang);
    g_sin[idx] = sinf(ang);
}

// ---------------------------------------------------------------------------
// TF32 mma.sync GEMM: out[M,N] = A[M,K] @ Bw[K,N] + bias[N]   (verified R3)
// ---------------------------------------------------------------------------
constexpr int APAD = 36;
constexpr int BPAD = 136;

__global__ __launch_bounds__(256) void mma_gemm_kernel(
    const float* __restrict__ A, const float* __restrict__ Bw,
    const float* __restrict__ bias, float* __restrict__ out,
    int M, int N, int K, int mode)
{
    __shared__ float As[128 * APAD];
    __shared__ float Bs[32 * BPAD];

    const int tid = threadIdx.x;
    const int lane = tid & 31;
    const int wid = tid >> 5;
    const int wm = wid >> 2;
    const int wn = wid & 3;
    const int mBase = blockIdx.y * 128;
    const int nBase = blockIdx.x * 128;
    const int g4 = lane >> 2;
    const int c4 = lane & 3;

    float acc[4][4][4] = {};
    float4 aS[4], bS[4];

    auto load_tiles = [&](int it) {
        const int k0 = it * 32;
#pragma unroll
        for (int p = 0; p < 4; p++) {
            int v = p * 256 + tid;
            int ar = v >> 3, ac = (v & 7) * 4;
            aS[p] = *(const float4*)(A + (size_t)(mBase + ar) * K + k0 + ac);
            int br = v >> 5, bc = (v & 31) * 4;
            bS[p] = *(const float4*)(Bw + (size_t)(k0 + br) * N + nBase + bc);
        }
    };
    auto store_tiles = [&]() {
#pragma unroll
        for (int p = 0; p < 4; p++) {
            int v = p * 256 + tid;
            int ar = v >> 3, ac = (v & 7) * 4;
            uint32_t* ad = (uint32_t*)&As[ar * APAD + ac];
            ad[0] = f2tf32(aS[p].x); ad[1] = f2tf32(aS[p].y);
            ad[2] = f2tf32(aS[p].z); ad[3] = f2tf32(aS[p].w);
            int br = v >> 5, bc = (v & 31) * 4;
            uint32_t* bd = (uint32_t*)&Bs[br * BPAD + bc];
            bd[0] = f2tf32(bS[p].x); bd[1] = f2tf32(bS[p].y);
            bd[2] = f2tf32(bS[p].z); bd[3] = f2tf32(bS[p].w);
        }
    };

    const uint32_t* As32 = (const uint32_t*)As;
    const uint32_t* Bs32 = (const uint32_t*)Bs;
    const int KT = K / 32;

    load_tiles(0);
    for (int it = 0; it < KT; it++) {
        store_tiles();
        __syncthreads();
        if (it + 1 < KT) load_tiles(it + 1);

#pragma unroll
        for (int ks = 0; ks < 4; ks++) {
            const int kk = ks * 8;
            uint32_t af[4][4];
#pragma unroll
            for (int mt = 0; mt < 4; mt++) {
                int m = wm * 64 + mt * 16 + g4;
                af[mt][0] = As32[m * APAD + kk + c4];
                af[mt][1] = As32[(m + 8) * APAD + kk + c4];
                af[mt][2] = As32[m * APAD + kk + 4 + c4];
                af[mt][3] = As32[(m + 8) * APAD + kk + 4 + c4];
            }
            uint32_t bf[4][2];
#pragma unroll
            for (int nt = 0; nt < 4; nt++) {
                int n = wn * 32 + nt * 8 + g4;
                bf[nt][0] = Bs32[(kk + c4) * BPAD + n];
                bf[nt][1] = Bs32[(kk + 4 + c4) * BPAD + n];
            }
#pragma unroll
            for (int mt = 0; mt < 4; mt++)
#pragma unroll
                for (int nt = 0; nt < 4; nt++)
                    mma_tf32(acc[mt][nt], af[mt], bf[nt]);
        }
        __syncthreads();
    }

#pragma unroll
    for (int mt = 0; mt < 4; mt++) {
#pragma unroll
        for (int nt = 0; nt < 4; nt++) {
            const int col = nBase + wn * 32 + nt * 8 + 2 * c4;
            const float b0 = __ldg(&bias[col]);
            const float b1 = __ldg(&bias[col + 1]);
            const int row0 = mBase + wm * 64 + mt * 16 + g4;

            float v00 = acc[mt][nt][0] + b0, v01 = acc[mt][nt][1] + b1;
            float v10 = acc[mt][nt][2] + b0, v11 = acc[mt][nt][3] + b1;

            if (mode == 0) {
                *(float2*)(out + (size_t)row0 * N + col) = make_float2(v00, v01);
                *(float2*)(out + (size_t)(row0 + 8) * N + col) = make_float2(v10, v11);
            } else {
                const int part = col >> 10;
                const int h = (col & 1023) >> 6;
                const int d = col & 63;
                const int i = d >> 1;
                const int b = row0 >> 11;
                const int t0 = row0 & (Tt - 1);
                const int t1 = (row0 + 8) & (Tt - 1);
                if (part < 2) {
                    float co0 = g_cos[t0 * 32 + i], si0 = g_sin[t0 * 32 + i];
                    float co1 = g_cos[t1 * 32 + i], si1 = g_sin[t1 * 32 + i];
                    float r00 = v00 * co0 - v01 * si0;
                    float r01 = v01 * co0 + v00 * si0;
                    float r10 = v10 * co1 - v11 * si1;
                    float r11 = v11 * co1 + v10 * si1;
                    v00 = r00; v01 = r01; v10 = r10; v11 = r11;
                }
                float* dst = (part == 0) ? g_q : (part == 1) ? g_k : g_v;
                size_t base = ((size_t)(b * Hh + h)) * Tt;
                *(float2*)(dst + (base + t0) * Dd + d) = make_float2(v00, v01);
                *(float2*)(dst + (base + t1) * Dd + d) = make_float2(v10, v11);
            }
        }
    }
}

// ---------------------------------------------------------------------------
// Flash attention (causal) with tf32 mma.sync tensor cores.
// 256 threads = 8 warps; CTA = 128 queries; 64-key tiles.
// Each warp owns 16 query rows. P kept in registers via shfl permutation.
// ---------------------------------------------------------------------------
constexpr int KSP = 68;   // K smem row pitch (floats)
constexpr int VSP = 72;   // V smem row pitch (floats)

__global__ __launch_bounds__(256) void flash_mma_kernel(
    const float* __restrict__ Q, const float* __restrict__ K,
    const float* __restrict__ V, float* __restrict__ Y)
{
    __shared__ uint32_t Ks[64 * KSP];
    __shared__ uint32_t Vs[64 * VSP];

    const int tid = threadIdx.x;
    const int lane = tid & 31;
    const int w = tid >> 5;
    const int g4 = lane >> 2;
    const int c4 = lane & 3;
    const int e = c4 & 1;

    const int bh = blockIdx.y;
    const int m0 = blockIdx.x * 128;
    const int wRow0 = m0 + w * 16;
    const int qr0 = wRow0 + g4;
    const int qr1 = qr0 + 8;

    const float* Qb = Q + (size_t)bh * Tt * Dd;
    const float* Kb = K + (size_t)bh * Tt * Dd;
    const float* Vb = V + (size_t)bh * Tt * Dd;

    // Q fragments (scaled by 1/sqrt(D)=0.125), loaded once
    uint32_t qf[8][4];
    {
        const float* q0 = Qb + (size_t)qr0 * Dd;
        const float* q1 = Qb + (size_t)qr1 * Dd;
#pragma unroll
        for (int kc = 0; kc < 8; kc++) {
            qf[kc][0] = f2tf32(q0[kc * 8 + c4] * 0.125f);
            qf[kc][1] = f2tf32(q1[kc * 8 + c4] * 0.125f);
            qf[kc][2] = f2tf32(q0[kc * 8 + c4 + 4] * 0.125f);
            qf[kc][3] = f2tf32(q1[kc * 8 + c4 + 4] * 0.125f);
        }
    }

    float o[8][4] = {};
    float mrun0 = -1e30f, mrun1 = -1e30f, l0 = 0.f, l1 = 0.f;

    const int jend = m0 + 128;
    float4 kReg[4], vReg[4];

    auto ldtile = [&](int j0) {
#pragma unroll
        for (int p = 0; p < 4; p++) {
            int v = p * 256 + tid;
            int r = v >> 4, c = (v & 15) * 4;
            kReg[p] = *(const float4*)(Kb + (size_t)(j0 + r) * Dd + c);
            vReg[p] = *(const float4*)(Vb + (size_t)(j0 + r) * Dd + c);
        }
    };

    ldtile(0);
    for (int j0 = 0; j0 < jend; j0 += 64) {
        if (j0) __syncthreads();
#pragma unroll
        for (int p = 0; p < 4; p++) {
            int v = p * 256 + tid;
            int r = v >> 4, c = (v & 15) * 4;
            uint4 kt = make_uint4(f2tf32(kReg[p].x), f2tf32(kReg[p].y),
                                  f2tf32(kReg[p].z), f2tf32(kReg[p].w));
            uint4 vt = make_uint4(f2tf32(vReg[p].x), f2tf32(vReg[p].y),
                                  f2tf32(vReg[p].z), f2tf32(vReg[p].w));
            *(uint4*)&Ks[r * KSP + c] = kt;
            *(uint4*)&Vs[r * VSP + c] = vt;
        }
        __syncthreads();
        if (j0 + 64 < jend) ldtile(j0 + 64);

        if (j0 <= wRow0 + 15) {     // warp-uniform: skip fully-masked tiles
            // --- S = Q @ K^T ---
            float s[8][4] = {};
#pragma unroll
            for (int kc = 0; kc < 8; kc++) {
#pragma unroll
                for (int nt = 0; nt < 8; nt++) {
                    uint32_t bf[2];
                    bf[0] = Ks[(nt * 8 + g4) * KSP + kc * 8 + c4];
                    bf[1] = Ks[(nt * 8 + g4) * KSP + kc * 8 + c4 + 4];
                    mma_tf32(s[nt], qf[kc], bf);
                }
            }

            // --- causal mask (boundary tiles only) ---
            if (j0 + 63 > wRow0) {
#pragma unroll
                for (int nt = 0; nt < 8; nt++) {
                    int cb = j0 + nt * 8 + 2 * c4;
                    if (cb > qr0)     s[nt][0] = -1e30f;
                    if (cb + 1 > qr0) s[nt][1] = -1e30f;
                    if (cb > qr1)     s[nt][2] = -1e30f;
                    if (cb + 1 > qr1) s[nt][3] = -1e30f;
                }
            }

            // --- online softmax ---
            float mx0 = -1e30f, mx1 = -1e30f;
#pragma unroll
            for (int nt = 0; nt < 8; nt++) {
                mx0 = fmaxf(mx0, fmaxf(s[nt][0], s[nt][1]));
                mx1 = fmaxf(mx1, fmaxf(s[nt][2], s[nt][3]));
            }
            mx0 = fmaxf(mx0, __shfl_xor_sync(0xffffffffu, mx0, 1));
            mx0 = fmaxf(mx0, __shfl_xor_sync(0xffffffffu, mx0, 2));
            mx1 = fmaxf(mx1, __shfl_xor_sync(0xffffffffu, mx1, 1));
            mx1 = fmaxf(mx1, __shfl_xor_sync(0xffffffffu, mx1, 2));

            float mn0 = fmaxf(mrun0, mx0), mn1 = fmaxf(mrun1, mx1);
            float corr0 = __expf(mrun0 - mn0), corr1 = __expf(mrun1 - mn1);
            mrun0 = mn0; mrun1 = mn1;

            float sum0 = 0.f, sum1 = 0.f;
#pragma unroll
            for (int nt = 0; nt < 8; nt++) {
                float p0 = __expf(s[nt][0] - mn0);
                float p1 = __expf(s[nt][1] - mn0);
                float p2 = __expf(s[nt][2] - mn1);
                float p3 = __expf(s[nt][3] - mn1);
                sum0 += p0 + p1;
                sum1 += p2 + p3;
                s[nt][0] = __uint_as_float(f2tf32(p0));
                s[nt][1] = __uint_as_float(f2tf32(p1));
                s[nt][2] = __uint_as_float(f2tf32(p2));
                s[nt][3] = __uint_as_float(f2tf32(p3));
            }
            sum0 += __shfl_xor_sync(0xffffffffu, sum0, 1);
            sum0 += __shfl_xor_sync(0xffffffffu, sum0, 2);
            sum1 += __shfl_xor_sync(0xffffffffu, sum1, 1);
            sum1 += __shfl_xor_sync(0xffffffffu, sum1, 2);
            l0 = l0 * corr0 + sum0;
            l1 = l1 * corr1 + sum1;
#pragma unroll
            for (int nt = 0; nt < 8; nt++) {
                o[nt][0] *= corr0; o[nt][1] *= corr0;
                o[nt][2] *= corr1; o[nt][3] *= corr1;
            }

            // --- O += P @ V  (P permuted from S-acc layout via shfl) ---
            const int srcA = (lane & 28) + (c4 >> 1);
#pragma unroll
            for (int kc = 0; kc < 8; kc++) {
                float s0 = __shfl_sync(0xffffffffu, s[kc][0], srcA);
                float s1 = __shfl_sync(0xffffffffu, s[kc][1], srcA);
                float s2 = __shfl_sync(0xffffffffu, s[kc][2], srcA);
                float s3 = __shfl_sync(0xffffffffu, s[kc][3], srcA);
                float t0 = __shfl_sync(0xffffffffu, s[kc][0], srcA + 2);
                float t1 = __shfl_sync(0xffffffffu, s[kc][1], srcA + 2);
                float t2 = __shfl_sync(0xffffffffu, s[kc][2], srcA + 2);
                float t3 = __shfl_sync(0xffffffffu, s[kc][3], srcA + 2);
                uint32_t a[4];
                a[0] = __float_as_uint(e ? s1 : s0);
                a[1] = __float_as_uint(e ? s3 : s2);
                a[2] = __float_as_uint(e ? t1 : t0);
                a[3] = __float_as_uint(e ? t3 : t2);
#pragma unroll
                for (int nt = 0; nt < 8; nt++) {
                    uint32_t bf[2];
                    bf[0] = Vs[(kc * 8 + c4) * VSP + nt * 8 + g4];
                    bf[1] = Vs[(kc * 8 + 4 + c4) * VSP + nt * 8 + g4];
                    mma_tf32(o[nt], a, bf);
                }
            }
        }
    }

    // epilogue: normalize + write to Y[B,T,C] at head h
    const float inv0 = 1.f / l0;
    const float inv1 = 1.f / l1;
    const int b = bh >> 4;
    const int h = bh & 15;
    float* y0 = Y + ((size_t)(b * Tt + qr0)) * Cc + h * Dd;
    float* y1 = Y + ((size_t)(b * Tt + qr1)) * Cc + h * Dd;
#pragma unroll
    for (int nt = 0; nt < 8; nt++) {
        int dc = nt * 8 + 2 * c4;
        *(float2*)(y0 + dc) = make_float2(o[nt][0] * inv0, o[nt][1] * inv0);
        *(float2*)(y1 + dc) = make_float2(o[nt][2] * inv1, o[nt][3] * inv1);
    }
}

// ---------------------------------------------------------------------------
// launch
// ---------------------------------------------------------------------------
extern "C" void kernel_launch(void* const* d_in, const int* in_sizes, int n_in,
                              void* d_out, int out_size) {
    const float* x      = (const float*)d_in[0];
    const float* w_attn = (const float*)d_in[1];
    const float* b_attn = (const float*)d_in[2];
    const float* w_proj = (const float*)d_in[3];
    const float* b_proj = (const float*)d_in[4];
    float* out = (float*)d_out;

    float *q, *k, *v, *y;
    cudaGetSymbolAddress((void**)&q, g_q);
    cudaGetSymbolAddress((void**)&k, g_k);
    cudaGetSymbolAddress((void**)&v, g_v);
    cudaGetSymbolAddress((void**)&y, g_y);

    // RoPE table
    {
        int total = Tt * (Dd / 2);
        rope_table_kernel<<<(total + 255) / 256, 256>>>();
    }
    // QKV GEMM (tf32 mma.sync) with fused bias + RoPE + head scatter
    mma_gemm_kernel<<<dim3(N3C / 128, Mrows / 128), 256>>>(
        x, w_attn, b_attn, nullptr, Mrows, N3C, Cc, 1);
    // Flash attention (tf32 mma.sync)
    flash_mma_kernel<<<dim3(Tt / 128, Bb * Hh), 256>>>(q, k, v, y);
    // Output projection (tf32 mma.sync) with fused bias
    mma_gemm_kernel<<<dim3(Cc / 128, Mrows / 128), 256>>>(
        y, w_proj, b_proj, out, Mrows, Cc, Cc, 0);
}

// round 6
// speedup vs baseline: 5.1718x; 1.2773x over previous
#include <cuda_runtime.h>
#include <cuda_fp16.h>
#include <cstdint>

// Problem constants
constexpr int Bb = 2;
constexpr int Tt = 2048;
constexpr int Cc = 1024;
constexpr int Hh = 16;
constexpr int Dd = 64;
constexpr int Mrows = Bb * Tt;        // 4096
constexpr int N3C = 3 * Cc;           // 3072

// Scratch (static device memory)
// Q/K/V as packed fp16x2 words: [B,H,T,D/2] (Q pre-scaled by 1/sqrt(D))
__device__ uint32_t g_qh[Bb * Hh * Tt * 32];
__device__ uint32_t g_kh[Bb * Hh * Tt * 32];
__device__ uint32_t g_vh[Bb * Hh * Tt * 32];
__device__ float g_y[Mrows * Cc];
__device__ float g_cos[Tt * (Dd / 2)];
__device__ float g_sin[Tt * (Dd / 2)];

__device__ __forceinline__ uint32_t f2tf32(float x) {
    uint32_t r; asm("cvt.rna.tf32.f32 %0, %1;" : "=r"(r) : "f"(x)); return r;
}
__device__ __forceinline__ uint32_t packhf(float lo, float hi) {
    uint32_t r; asm("cvt.rn.f16x2.f32 %0, %1, %2;" : "=r"(r) : "f"(hi), "f"(lo));
    return r;
}

__device__ __forceinline__ void mma_tf32(float* c, const uint32_t* a, const uint32_t* b) {
    asm volatile(
        "mma.sync.aligned.m16n8k8.row.col.f32.tf32.tf32.f32 "
        "{%0,%1,%2,%3}, {%4,%5,%6,%7}, {%8,%9}, {%0,%1,%2,%3};"
        : "+f"(c[0]), "+f"(c[1]), "+f"(c[2]), "+f"(c[3])
        : "r"(a[0]), "r"(a[1]), "r"(a[2]), "r"(a[3]), "r"(b[0]), "r"(b[1]));
}
__device__ __forceinline__ void mma_f16(float* c, const uint32_t* a, const uint32_t* b) {
    asm volatile(
        "mma.sync.aligned.m16n8k16.row.col.f32.f16.f16.f32 "
        "{%0,%1,%2,%3}, {%4,%5,%6,%7}, {%8,%9}, {%0,%1,%2,%3};"
        : "+f"(c[0]), "+f"(c[1]), "+f"(c[2]), "+f"(c[3])
        : "r"(a[0]), "r"(a[1]), "r"(a[2]), "r"(a[3]), "r"(b[0]), "r"(b[1]));
}

#define LDSM_X4(r0, r1, r2, r3, addr) \
    asm volatile("ldmatrix.sync.aligned.m8n8.x4.shared.b16 {%0,%1,%2,%3}, [%4];" \
                 : "=r"(r0), "=r"(r1), "=r"(r2), "=r"(r3) : "r"(addr))
#define LDSM_X4_T(r0, r1, r2, r3, addr) \
    asm volatile("ldmatrix.sync.aligned.m8n8.x4.trans.shared.b16 {%0,%1,%2,%3}, [%4];" \
                 : "=r"(r0), "=r"(r1), "=r"(r2), "=r"(r3) : "r"(addr))
#define CP_ASYNC16(dst, src) \
    asm volatile("cp.async.cg.shared.global [%0], [%1], 16;" :: "r"(dst), "l"(src))
#define CP_COMMIT() asm volatile("cp.async.commit_group;" ::: "memory")
#define CP_WAIT(n)  asm volatile("cp.async.wait_group %0;" :: "n"(n) : "memory")

// ---------------------------------------------------------------------------
// RoPE table
// ---------------------------------------------------------------------------
__global__ void rope_table_kernel() {
    int idx = blockIdx.x * blockDim.x + threadIdx.x;
    if (idx >= Tt * (Dd / 2)) return;
    int t = idx / (Dd / 2);
    int i = idx % (Dd / 2);
    double inv = exp(-((double)(2 * i) / (double)Dd) * log(10000.0));
    float ang = (float)((double)t * inv);
    g_cos[idx] = cosf(ang);
    g_sin[idx] = sinf(ang);
}

// ---------------------------------------------------------------------------
// TF32 mma.sync GEMM (verified R3/R4). mode 1 epilogue emits fp16 QKV.
// ---------------------------------------------------------------------------
constexpr int APAD = 36;
constexpr int BPAD = 136;

__global__ __launch_bounds__(256) void mma_gemm_kernel(
    const float* __restrict__ A, const float* __restrict__ Bw,
    const float* __restrict__ bias, float* __restrict__ out,
    int M, int N, int K, int mode)
{
    __shared__ float As[128 * APAD];
    __shared__ float Bs[32 * BPAD];

    const int tid = threadIdx.x;
    const int lane = tid & 31;
    const int wid = tid >> 5;
    const int wm = wid >> 2;
    const int wn = wid & 3;
    const int mBase = blockIdx.y * 128;
    const int nBase = blockIdx.x * 128;
    const int g4 = lane >> 2;
    const int c4 = lane & 3;

    float acc[4][4][4] = {};
    float4 aS[4], bS[4];

    auto load_tiles = [&](int it) {
        const int k0 = it * 32;
#pragma unroll
        for (int p = 0; p < 4; p++) {
            int v = p * 256 + tid;
            int ar = v >> 3, ac = (v & 7) * 4;
            aS[p] = *(const float4*)(A + (size_t)(mBase + ar) * K + k0 + ac);
            int br = v >> 5, bc = (v & 31) * 4;
            bS[p] = *(const float4*)(Bw + (size_t)(k0 + br) * N + nBase + bc);
        }
    };
    auto store_tiles = [&]() {
#pragma unroll
        for (int p = 0; p < 4; p++) {
            int v = p * 256 + tid;
            int ar = v >> 3, ac = (v & 7) * 4;
            uint32_t* ad = (uint32_t*)&As[ar * APAD + ac];
            ad[0] = f2tf32(aS[p].x); ad[1] = f2tf32(aS[p].y);
            ad[2] = f2tf32(aS[p].z); ad[3] = f2tf32(aS[p].w);
            int br = v >> 5, bc = (v & 31) * 4;
            uint32_t* bd = (uint32_t*)&Bs[br * BPAD + bc];
            bd[0] = f2tf32(bS[p].x); bd[1] = f2tf32(bS[p].y);
            bd[2] = f2tf32(bS[p].z); bd[3] = f2tf32(bS[p].w);
        }
    };

    const uint32_t* As32 = (const uint32_t*)As;
    const uint32_t* Bs32 = (const uint32_t*)Bs;
    const int KT = K / 32;

    load_tiles(0);
    for (int it = 0; it < KT; it++) {
        store_tiles();
        __syncthreads();
        if (it + 1 < KT) load_tiles(it + 1);

#pragma unroll
        for (int ks = 0; ks < 4; ks++) {
            const int kk = ks * 8;
            uint32_t af[4][4];
#pragma unroll
            for (int mt = 0; mt < 4; mt++) {
                int m = wm * 64 + mt * 16 + g4;
                af[mt][0] = As32[m * APAD + kk + c4];
                af[mt][1] = As32[(m + 8) * APAD + kk + c4];
                af[mt][2] = As32[m * APAD + kk + 4 + c4];
                af[mt][3] = As32[(m + 8) * APAD + kk + 4 + c4];
            }
            uint32_t bf[4][2];
#pragma unroll
            for (int nt = 0; nt < 4; nt++) {
                int n = wn * 32 + nt * 8 + g4;
                bf[nt][0] = Bs32[(kk + c4) * BPAD + n];
                bf[nt][1] = Bs32[(kk + 4 + c4) * BPAD + n];
            }
#pragma unroll
            for (int mt = 0; mt < 4; mt++)
#pragma unroll
                for (int nt = 0; nt < 4; nt++)
                    mma_tf32(acc[mt][nt], af[mt], bf[nt]);
        }
        __syncthreads();
    }

#pragma unroll
    for (int mt = 0; mt < 4; mt++) {
#pragma unroll
        for (int nt = 0; nt < 4; nt++) {
            const int col = nBase + wn * 32 + nt * 8 + 2 * c4;
            const float b0 = __ldg(&bias[col]);
            const float b1 = __ldg(&bias[col + 1]);
            const int row0 = mBase + wm * 64 + mt * 16 + g4;

            float v00 = acc[mt][nt][0] + b0, v01 = acc[mt][nt][1] + b1;
            float v10 = acc[mt][nt][2] + b0, v11 = acc[mt][nt][3] + b1;

            if (mode == 0) {
                *(float2*)(out + (size_t)row0 * N + col) = make_float2(v00, v01);
                *(float2*)(out + (size_t)(row0 + 8) * N + col) = make_float2(v10, v11);
            } else {
                const int part = col >> 10;
                const int h = (col & 1023) >> 6;
                const int d = col & 63;
                const int i = d >> 1;
                const int b = row0 >> 11;
                const int t0 = row0 & (Tt - 1);
                const int t1 = (row0 + 8) & (Tt - 1);
                if (part < 2) {
                    float co0 = g_cos[t0 * 32 + i], si0 = g_sin[t0 * 32 + i];
                    float co1 = g_cos[t1 * 32 + i], si1 = g_sin[t1 * 32 + i];
                    float r00 = v00 * co0 - v01 * si0;
                    float r01 = v01 * co0 + v00 * si0;
                    float r10 = v10 * co1 - v11 * si1;
                    float r11 = v11 * co1 + v10 * si1;
                    v00 = r00; v01 = r01; v10 = r10; v11 = r11;
                }
                if (part == 0) {           // fold 1/sqrt(D) into Q
                    v00 *= 0.125f; v01 *= 0.125f; v10 *= 0.125f; v11 *= 0.125f;
                }
                uint32_t* dst = (part == 0) ? g_qh : (part == 1) ? g_kh : g_vh;
                size_t base = ((size_t)(b * Hh + h)) * Tt;
                dst[(base + t0) * 32 + (d >> 1)] = packhf(v00, v01);
                dst[(base + t1) * 32 + (d >> 1)] = packhf(v10, v11);
            }
        }
    }
}

// ---------------------------------------------------------------------------
// Flash attention (causal), fp16 m16n8k16 + ldmatrix, cp.async double buffer.
// 256 threads = 8 warps; warp owns 16 query rows; CTA = 128 queries; 64-key tiles.
// ---------------------------------------------------------------------------
constexpr int KP = 72;   // fp16 row pitch (144 B): conflict-free ldmatrix

__global__ __launch_bounds__(256) void flash_f16_kernel(
    const uint32_t* __restrict__ Qh, const uint32_t* __restrict__ Kh,
    const uint32_t* __restrict__ Vh, float* __restrict__ Y)
{
    __shared__ __half Ks[2][64 * KP];
    __shared__ __half Vs[2][64 * KP];

    const int tid = threadIdx.x;
    const int lane = tid & 31;
    const int w = tid >> 5;
    const int g4 = lane >> 2;
    const int c4 = lane & 3;

    const int bh = blockIdx.y;
    const int m0 = blockIdx.x * 128;
    const int wRow0 = m0 + w * 16;
    const int qr0 = wRow0 + g4;
    const int qr1 = qr0 + 8;

    const uint32_t* Qb = Qh + (size_t)bh * Tt * 32;
    const uint32_t* Kb = Kh + (size_t)bh * Tt * 32;
    const uint32_t* Vb = Vh + (size_t)bh * Tt * 32;

    // Q A-fragments (fp16, pre-scaled), 4 k16-blocks x 4 regs
    uint32_t qf[4][4];
    {
        const uint32_t* q0 = Qb + (size_t)qr0 * 32;
        const uint32_t* q1 = Qb + (size_t)qr1 * 32;
#pragma unroll
        for (int kc = 0; kc < 4; kc++) {
            qf[kc][0] = q0[kc * 8 + c4];
            qf[kc][1] = q1[kc * 8 + c4];
            qf[kc][2] = q0[kc * 8 + c4 + 4];
            qf[kc][3] = q1[kc * 8 + c4 + 4];
        }
    }

    float o[8][4] = {};
    float mrun0 = -1e30f, mrun1 = -1e30f, l0 = 0.f, l1 = 0.f;

    const int ntiles = (m0 + 128) / 64;

    auto prefetch = [&](int it) {
        const int j0 = it * 64;
        const int buf = it & 1;
#pragma unroll
        for (int p = 0; p < 2; p++) {
            int id = p * 256 + tid;
            int r = id >> 3, ch = id & 7;
            uint32_t kd = (uint32_t)__cvta_generic_to_shared(
                &Ks[buf][r * KP + ch * 8]);
            uint32_t vd = (uint32_t)__cvta_generic_to_shared(
                &Vs[buf][r * KP + ch * 8]);
            const char* ksrc = (const char*)(Kb + (size_t)(j0 + r) * 32 + ch * 4);
            const char* vsrc = (const char*)(Vb + (size_t)(j0 + r) * 32 + ch * 4);
            CP_ASYNC16(kd, ksrc);
            CP_ASYNC16(vd, vsrc);
        }
        CP_COMMIT();
    };

    prefetch(0);

    for (int it = 0; it < ntiles; it++) {
        const int j0 = it * 64;
        const int buf = it & 1;
        const bool has_next = (it + 1 < ntiles);
        if (has_next) { prefetch(it + 1); CP_WAIT(1); }
        else          { CP_WAIT(0); }
        __syncthreads();

        if (j0 <= wRow0 + 15) {
            // ---- S = Q @ K^T ----
            float s[8][4] = {};
#pragma unroll
            for (int nt = 0; nt < 8; nt++) {
                uint32_t kb[8];
                uint32_t a0 = (uint32_t)__cvta_generic_to_shared(
                    &Ks[buf][(nt * 8 + (lane & 7)) * KP + ((lane >> 3) & 3) * 8]);
                LDSM_X4(kb[0], kb[1], kb[2], kb[3], a0);
                uint32_t a1 = (uint32_t)__cvta_generic_to_shared(
                    &Ks[buf][(nt * 8 + (lane & 7)) * KP + 32 + ((lane >> 3) & 3) * 8]);
                LDSM_X4(kb[4], kb[5], kb[6], kb[7], a1);
#pragma unroll
                for (int kc = 0; kc < 4; kc++)
                    mma_f16(s[nt], qf[kc], &kb[kc * 2]);
            }

            // ---- causal mask (boundary tiles only) ----
            if (j0 + 63 > wRow0) {
#pragma unroll
                for (int nt = 0; nt < 8; nt++) {
                    int cb = j0 + nt * 8 + 2 * c4;
                    if (cb > qr0)     s[nt][0] = -1e30f;
                    if (cb + 1 > qr0) s[nt][1] = -1e30f;
                    if (cb > qr1)     s[nt][2] = -1e30f;
                    if (cb + 1 > qr1) s[nt][3] = -1e30f;
                }
            }

            // ---- online softmax ----
            float mx0 = -1e30f, mx1 = -1e30f;
#pragma unroll
            for (int nt = 0; nt < 8; nt++) {
                mx0 = fmaxf(mx0, fmaxf(s[nt][0], s[nt][1]));
                mx1 = fmaxf(mx1, fmaxf(s[nt][2], s[nt][3]));
            }
            mx0 = fmaxf(mx0, __shfl_xor_sync(0xffffffffu, mx0, 1));
            mx0 = fmaxf(mx0, __shfl_xor_sync(0xffffffffu, mx0, 2));
            mx1 = fmaxf(mx1, __shfl_xor_sync(0xffffffffu, mx1, 1));
            mx1 = fmaxf(mx1, __shfl_xor_sync(0xffffffffu, mx1, 2));

            float mn0 = fmaxf(mrun0, mx0), mn1 = fmaxf(mrun1, mx1);
            float corr0 = __expf(mrun0 - mn0), corr1 = __expf(mrun1 - mn1);
            mrun0 = mn0; mrun1 = mn1;

            float sum0 = 0.f, sum1 = 0.f;
#pragma unroll
            for (int nt = 0; nt < 8; nt++) {
                s[nt][0] = __expf(s[nt][0] - mn0);
                s[nt][1] = __expf(s[nt][1] - mn0);
                s[nt][2] = __expf(s[nt][2] - mn1);
                s[nt][3] = __expf(s[nt][3] - mn1);
                sum0 += s[nt][0] + s[nt][1];
                sum1 += s[nt][2] + s[nt][3];
            }
            sum0 += __shfl_xor_sync(0xffffffffu, sum0, 1);
            sum0 += __shfl_xor_sync(0xffffffffu, sum0, 2);
            sum1 += __shfl_xor_sync(0xffffffffu, sum1, 1);
            sum1 += __shfl_xor_sync(0xffffffffu, sum1, 2);
            l0 = l0 * corr0 + sum0;
            l1 = l1 * corr1 + sum1;
#pragma unroll
            for (int nt = 0; nt < 8; nt++) {
                o[nt][0] *= corr0; o[nt][1] *= corr0;
                o[nt][2] *= corr1; o[nt][3] *= corr1;
            }

            // ---- O += P @ V  (P packs directly into A-frags; V via ldmatrix.trans)
#pragma unroll
            for (int kcb = 0; kcb < 4; kcb++) {
                uint32_t pa[4];
                pa[0] = packhf(s[2 * kcb][0], s[2 * kcb][1]);
                pa[1] = packhf(s[2 * kcb][2], s[2 * kcb][3]);
                pa[2] = packhf(s[2 * kcb + 1][0], s[2 * kcb + 1][1]);
                pa[3] = packhf(s[2 * kcb + 1][2], s[2 * kcb + 1][3]);
#pragma unroll
                for (int db = 0; db < 4; db++) {
                    uint32_t vb[4];
                    uint32_t va = (uint32_t)__cvta_generic_to_shared(
                        &Vs[buf][(kcb * 16 + (lane & 15)) * KP + db * 16 + (lane >> 4) * 8]);
                    LDSM_X4_T(vb[0], vb[1], vb[2], vb[3], va);
                    mma_f16(o[db * 2],     pa, &vb[0]);
                    mma_f16(o[db * 2 + 1], pa, &vb[2]);
                }
            }
        }
        __syncthreads();   // compute done before next prefetch overwrites buf^1
    }

    // epilogue: normalize + write fp32 to Y[B,T,C] at head h
    const float inv0 = 1.f / l0;
    const float inv1 = 1.f / l1;
    const int b = bh >> 4;
    const int h = bh & 15;
    float* y0 = Y + ((size_t)(b * Tt + qr0)) * Cc + h * Dd;
    float* y1 = Y + ((size_t)(b * Tt + qr1)) * Cc + h * Dd;
#pragma unroll
    for (int nt = 0; nt < 8; nt++) {
        int dc = nt * 8 + 2 * c4;
        *(float2*)(y0 + dc) = make_float2(o[nt][0] * inv0, o[nt][1] * inv0);
        *(float2*)(y1 + dc) = make_float2(o[nt][2] * inv1, o[nt][3] * inv1);
    }
}

// ---------------------------------------------------------------------------
// launch
// ---------------------------------------------------------------------------
extern "C" void kernel_launch(void* const* d_in, const int* in_sizes, int n_in,
                              void* d_out, int out_size) {
    const float* x      = (const float*)d_in[0];
    const float* w_attn = (const float*)d_in[1];
    const float* b_attn = (const float*)d_in[2];
    const float* w_proj = (const float*)d_in[3];
    const float* b_proj = (const float*)d_in[4];
    float* out = (float*)d_out;

    uint32_t *qh, *kh, *vh;
    float *y;
    cudaGetSymbolAddress((void**)&qh, g_qh);
    cudaGetSymbolAddress((void**)&kh, g_kh);
    cudaGetSymbolAddress((void**)&vh, g_vh);
    cudaGetSymbolAddress((void**)&y, g_y);

    // RoPE table
    {
        int total = Tt * (Dd / 2);
        rope_table_kernel<<<(total + 255) / 256, 256>>>();
    }
    // QKV GEMM (tf32 mma.sync) with fused bias + RoPE + fp16 head scatter
    mma_gemm_kernel<<<dim3(N3C / 128, Mrows / 128), 256>>>(
        x, w_attn, b_attn, nullptr, Mrows, N3C, Cc, 1);
    // Flash attention (fp16 m16n8k16 + ldmatrix)
    flash_f16_kernel<<<dim3(Tt / 128, Bb * Hh), 256>>>(qh, kh, vh, y);
    // Output projection (tf32 mma.sync) with fused bias
    mma_gemm_kernel<<<dim3(Cc / 128, Mrows / 128), 256>>>(
        y, w_proj, b_proj, out, Mrows, Cc, Cc, 0);
}

// round 7
// speedup vs baseline: 5.6879x; 1.0998x over previous
#include <cuda_runtime.h>
#include <cuda_fp16.h>
#include <cstdint>

// Problem constants
constexpr int Bb = 2;
constexpr int Tt = 2048;
constexpr int Cc = 1024;
constexpr int Hh = 16;
constexpr int Dd = 64;
constexpr int Mrows = Bb * Tt;        // 4096
constexpr int N3C = 3 * Cc;           // 3072

// Scratch (static device memory)
// Q/K/V as packed fp16x2 words: [B,H,T,D/2]
// Q pre-scaled by log2(e)/sqrt(D) so softmax works in exp2 domain.
__device__ uint32_t g_qh[Bb * Hh * Tt * 32];
__device__ uint32_t g_kh[Bb * Hh * Tt * 32];
__device__ uint32_t g_vh[Bb * Hh * Tt * 32];
__device__ float g_y[Mrows * Cc];
__device__ float g_cos[Tt * (Dd / 2)];
__device__ float g_sin[Tt * (Dd / 2)];

__device__ __forceinline__ uint32_t f2tf32(float x) {
    uint32_t r; asm("cvt.rna.tf32.f32 %0, %1;" : "=r"(r) : "f"(x)); return r;
}
__device__ __forceinline__ uint32_t packhf(float lo, float hi) {
    uint32_t r; asm("cvt.rn.f16x2.f32 %0, %1, %2;" : "=r"(r) : "f"(hi), "f"(lo));
    return r;
}
__device__ __forceinline__ uint32_t ex2_h2(uint32_t x) {
    uint32_t r; asm("ex2.approx.f16x2 %0, %1;" : "=r"(r) : "r"(x)); return r;
}

__device__ __forceinline__ void mma_tf32(float* c, const uint32_t* a, const uint32_t* b) {
    asm volatile(
        "mma.sync.aligned.m16n8k8.row.col.f32.tf32.tf32.f32 "
        "{%0,%1,%2,%3}, {%4,%5,%6,%7}, {%8,%9}, {%0,%1,%2,%3};"
        : "+f"(c[0]), "+f"(c[1]), "+f"(c[2]), "+f"(c[3])
        : "r"(a[0]), "r"(a[1]), "r"(a[2]), "r"(a[3]), "r"(b[0]), "r"(b[1]));
}
__device__ __forceinline__ void mma_f16(float* c, const uint32_t* a, const uint32_t* b) {
    asm volatile(
        "mma.sync.aligned.m16n8k16.row.col.f32.f16.f16.f32 "
        "{%0,%1,%2,%3}, {%4,%5,%6,%7}, {%8,%9}, {%0,%1,%2,%3};"
        : "+f"(c[0]), "+f"(c[1]), "+f"(c[2]), "+f"(c[3])
        : "r"(a[0]), "r"(a[1]), "r"(a[2]), "r"(a[3]), "r"(b[0]), "r"(b[1]));
}

#define LDSM_X4(r0, r1, r2, r3, addr) \
    asm volatile("ldmatrix.sync.aligned.m8n8.x4.shared.b16 {%0,%1,%2,%3}, [%4];" \
                 : "=r"(r0), "=r"(r1), "=r"(r2), "=r"(r3) : "r"(addr))
#define LDSM_X4_T(r0, r1, r2, r3, addr) \
    asm volatile("ldmatrix.sync.aligned.m8n8.x4.trans.shared.b16 {%0,%1,%2,%3}, [%4];" \
                 : "=r"(r0), "=r"(r1), "=r"(r2), "=r"(r3) : "r"(addr))
#define CP_ASYNC16(dst, src) \
    asm volatile("cp.async.cg.shared.global [%0], [%1], 16;" :: "r"(dst), "l"(src))
#define CP_COMMIT() asm volatile("cp.async.commit_group;" ::: "memory")
#define CP_WAIT(n)  asm volatile("cp.async.wait_group %0;" :: "n"(n) : "memory")

// ---------------------------------------------------------------------------
// RoPE table
// ---------------------------------------------------------------------------
__global__ void rope_table_kernel() {
    int idx = blockIdx.x * blockDim.x + threadIdx.x;
    if (idx >= Tt * (Dd / 2)) return;
    int t = idx / (Dd / 2);
    int i = idx % (Dd / 2);
    double inv = exp(-((double)(2 * i) / (double)Dd) * log(10000.0));
    float ang = (float)((double)t * inv);
    g_cos[idx] = cosf(ang);
    g_sin[idx] = sinf(ang);
}

// ---------------------------------------------------------------------------
// TF32 mma.sync GEMM (verified R3-R6). mode 1 epilogue emits fp16 QKV.
// ---------------------------------------------------------------------------
constexpr int APAD = 36;
constexpr int BPAD = 136;

__global__ __launch_bounds__(256) void mma_gemm_kernel(
    const float* __restrict__ A, const float* __restrict__ Bw,
    const float* __restrict__ bias, float* __restrict__ out,
    int M, int N, int K, int mode)
{
    __shared__ float As[128 * APAD];
    __shared__ float Bs[32 * BPAD];

    const int tid = threadIdx.x;
    const int lane = tid & 31;
    const int wid = tid >> 5;
    const int wm = wid >> 2;
    const int wn = wid & 3;
    const int mBase = blockIdx.y * 128;
    const int nBase = blockIdx.x * 128;
    const int g4 = lane >> 2;
    const int c4 = lane & 3;

    float acc[4][4][4] = {};
    float4 aS[4], bS[4];

    auto load_tiles = [&](int it) {
        const int k0 = it * 32;
#pragma unroll
        for (int p = 0; p < 4; p++) {
            int v = p * 256 + tid;
            int ar = v >> 3, ac = (v & 7) * 4;
            aS[p] = *(const float4*)(A + (size_t)(mBase + ar) * K + k0 + ac);
            int br = v >> 5, bc = (v & 31) * 4;
            bS[p] = *(const float4*)(Bw + (size_t)(k0 + br) * N + nBase + bc);
        }
    };
    auto store_tiles = [&]() {
#pragma unroll
        for (int p = 0; p < 4; p++) {
            int v = p * 256 + tid;
            int ar = v >> 3, ac = (v & 7) * 4;
            uint32_t* ad = (uint32_t*)&As[ar * APAD + ac];
            ad[0] = f2tf32(aS[p].x); ad[1] = f2tf32(aS[p].y);
            ad[2] = f2tf32(aS[p].z); ad[3] = f2tf32(aS[p].w);
            int br = v >> 5, bc = (v & 31) * 4;
            uint32_t* bd = (uint32_t*)&Bs[br * BPAD + bc];
            bd[0] = f2tf32(bS[p].x); bd[1] = f2tf32(bS[p].y);
            bd[2] = f2tf32(bS[p].z); bd[3] = f2tf32(bS[p].w);
        }
    };

    const uint32_t* As32 = (const uint32_t*)As;
    const uint32_t* Bs32 = (const uint32_t*)Bs;
    const int KT = K / 32;

    load_tiles(0);
    for (int it = 0; it < KT; it++) {
        store_tiles();
        __syncthreads();
        if (it + 1 < KT) load_tiles(it + 1);

#pragma unroll
        for (int ks = 0; ks < 4; ks++) {
            const int kk = ks * 8;
            uint32_t af[4][4];
#pragma unroll
            for (int mt = 0; mt < 4; mt++) {
                int m = wm * 64 + mt * 16 + g4;
                af[mt][0] = As32[m * APAD + kk + c4];
                af[mt][1] = As32[(m + 8) * APAD + kk + c4];
                af[mt][2] = As32[m * APAD + kk + 4 + c4];
                af[mt][3] = As32[(m + 8) * APAD + kk + 4 + c4];
            }
            uint32_t bf[4][2];
#pragma unroll
            for (int nt = 0; nt < 4; nt++) {
                int n = wn * 32 + nt * 8 + g4;
                bf[nt][0] = Bs32[(kk + c4) * BPAD + n];
                bf[nt][1] = Bs32[(kk + 4 + c4) * BPAD + n];
            }
#pragma unroll
            for (int mt = 0; mt < 4; mt++)
#pragma unroll
                for (int nt = 0; nt < 4; nt++)
                    mma_tf32(acc[mt][nt], af[mt], bf[nt]);
        }
        __syncthreads();
    }

#pragma unroll
    for (int mt = 0; mt < 4; mt++) {
#pragma unroll
        for (int nt = 0; nt < 4; nt++) {
            const int col = nBase + wn * 32 + nt * 8 + 2 * c4;
            const float b0 = __ldg(&bias[col]);
            const float b1 = __ldg(&bias[col + 1]);
            const int row0 = mBase + wm * 64 + mt * 16 + g4;

            float v00 = acc[mt][nt][0] + b0, v01 = acc[mt][nt][1] + b1;
            float v10 = acc[mt][nt][2] + b0, v11 = acc[mt][nt][3] + b1;

            if (mode == 0) {
                *(float2*)(out + (size_t)row0 * N + col) = make_float2(v00, v01);
                *(float2*)(out + (size_t)(row0 + 8) * N + col) = make_float2(v10, v11);
            } else {
                const int part = col >> 10;
                const int h = (col & 1023) >> 6;
                const int d = col & 63;
                const int i = d >> 1;
                const int b = row0 >> 11;
                const int t0 = row0 & (Tt - 1);
                const int t1 = (row0 + 8) & (Tt - 1);
                if (part < 2) {
                    float co0 = g_cos[t0 * 32 + i], si0 = g_sin[t0 * 32 + i];
                    float co1 = g_cos[t1 * 32 + i], si1 = g_sin[t1 * 32 + i];
                    float r00 = v00 * co0 - v01 * si0;
                    float r01 = v01 * co0 + v00 * si0;
                    float r10 = v10 * co1 - v11 * si1;
                    float r11 = v11 * co1 + v10 * si1;
                    v00 = r00; v01 = r01; v10 = r10; v11 = r11;
                }
                if (part == 0) {   // fold log2(e)/sqrt(D) into Q (exp2 domain)
                    const float qs = 0.18033688011111366f;
                    v00 *= qs; v01 *= qs; v10 *= qs; v11 *= qs;
                }
                uint32_t* dst = (part == 0) ? g_qh : (part == 1) ? g_kh : g_vh;
                size_t base = ((size_t)(b * Hh + h)) * Tt;
                dst[(base + t0) * 32 + (d >> 1)] = packhf(v00, v01);
                dst[(base + t1) * 32 + (d >> 1)] = packhf(v10, v11);
            }
        }
    }
}

// ---------------------------------------------------------------------------
// Flash attention (causal), fp16 mma + ldmatrix.
// 3-stage cp.async ring, ONE barrier per tile, exp2-domain softmax with
// f16x2 ex2 and row-sums via an all-ones B MMA. Work-descending 1D grid.
// ---------------------------------------------------------------------------
constexpr int KP = 72;                 // fp16 row pitch (144 B)
constexpr int STAGE_H = 2 * 64 * KP;   // halves per stage (K tile + V tile)
constexpr int FLASH_SMEM = 3 * STAGE_H * 2;  // bytes = 55296

__global__ __launch_bounds__(256) void flash_f16_kernel(
    const uint32_t* __restrict__ Qh, const uint32_t* __restrict__ Kh,
    const uint32_t* __restrict__ Vh, float* __restrict__ Y)
{
    extern __shared__ __half smf[];

    const int tid = threadIdx.x;
    const int lane = tid & 31;
    const int w = tid >> 5;
    const int g4 = lane >> 2;
    const int c4 = lane & 3;

    // work-descending mapping: big q-blocks first
    const int cta = blockIdx.x;
    const int bh = cta & 31;
    const int qb = (Tt / 128 - 1) - (cta >> 5);
    const int m0 = qb << 7;

    const int wRow0 = m0 + w * 16;
    const int qr0 = wRow0 + g4;
    const int qr1 = qr0 + 8;

    const uint32_t* Qb = Qh + (size_t)bh * Tt * 32;
    const uint32_t* Kb = Kh + (size_t)bh * Tt * 32;
    const uint32_t* Vb = Vh + (size_t)bh * Tt * 32;

    uint32_t qf[4][4];
    {
        const uint32_t* q0 = Qb + (size_t)qr0 * 32;
        const uint32_t* q1 = Qb + (size_t)qr1 * 32;
#pragma unroll
        for (int kc = 0; kc < 4; kc++) {
            qf[kc][0] = q0[kc * 8 + c4];
            qf[kc][1] = q1[kc * 8 + c4];
            qf[kc][2] = q0[kc * 8 + c4 + 4];
            qf[kc][3] = q1[kc * 8 + c4 + 4];
        }
    }

    float o[8][4] = {};
    float osum[4] = {};                 // row-sum accumulator (ones-column MMA)
    float mrun0 = -1e30f, mrun1 = -1e30f;

    const int ntiles = (m0 + 128) / 64;
    const uint32_t ones2[2] = {0x3C003C00u, 0x3C003C00u};

    auto prefetch = [&](int it) {
        const int j0 = it * 64;
        __half* Ks = smf + (it % 3) * STAGE_H;
        __half* Vs = Ks + 64 * KP;
#pragma unroll
        for (int p = 0; p < 2; p++) {
            int id = p * 256 + tid;
            int r = id >> 3, ch = id & 7;
            uint32_t kd = (uint32_t)__cvta_generic_to_shared(&Ks[r * KP + ch * 8]);
            uint32_t vd = (uint32_t)__cvta_generic_to_shared(&Vs[r * KP + ch * 8]);
            const char* ksrc = (const char*)(Kb + (size_t)(j0 + r) * 32 + ch * 4);
            const char* vsrc = (const char*)(Vb + (size_t)(j0 + r) * 32 + ch * 4);
            CP_ASYNC16(kd, ksrc);
            CP_ASYNC16(vd, vsrc);
        }
        CP_COMMIT();
    };

    prefetch(0);
    if (1 < ntiles) prefetch(1); else CP_COMMIT();

    for (int it = 0; it < ntiles; it++) {
        const int j0 = it * 64;
        __half* Ks = smf + (it % 3) * STAGE_H;
        __half* Vs = Ks + 64 * KP;

        CP_WAIT(1);
        __syncthreads();
        if (it + 2 < ntiles) prefetch(it + 2);

        if (j0 <= wRow0 + 15) {
            // ---- S = Q @ K^T ----
            float s[8][4] = {};
#pragma unroll
            for (int nt = 0; nt < 8; nt++) {
                uint32_t kb[8];
                uint32_t a0 = (uint32_t)__cvta_generic_to_shared(
                    &Ks[(nt * 8 + (lane & 7)) * KP + ((lane >> 3) & 3) * 8]);
                LDSM_X4(kb[0], kb[1], kb[2], kb[3], a0);
                uint32_t a1 = (uint32_t)__cvta_generic_to_shared(
                    &Ks[(nt * 8 + (lane & 7)) * KP + 32 + ((lane >> 3) & 3) * 8]);
                LDSM_X4(kb[4], kb[5], kb[6], kb[7], a1);
#pragma unroll
                for (int kc = 0; kc < 4; kc++)
                    mma_f16(s[nt], qf[kc], &kb[kc * 2]);
            }

            // ---- causal mask (boundary tiles only) ----
            if (j0 + 63 > wRow0) {
#pragma unroll
                for (int nt = 0; nt < 8; nt++) {
                    int cb = j0 + nt * 8 + 2 * c4;
                    if (cb > qr0)     s[nt][0] = -1e30f;
                    if (cb + 1 > qr0) s[nt][1] = -1e30f;
                    if (cb > qr1)     s[nt][2] = -1e30f;
                    if (cb + 1 > qr1) s[nt][3] = -1e30f;
                }
            }

            // ---- online softmax (exp2 domain) ----
            float mx0 = -1e30f, mx1 = -1e30f;
#pragma unroll
            for (int nt = 0; nt < 8; nt++) {
                mx0 = fmaxf(mx0, fmaxf(s[nt][0], s[nt][1]));
                mx1 = fmaxf(mx1, fmaxf(s[nt][2], s[nt][3]));
            }
            mx0 = fmaxf(mx0, __shfl_xor_sync(0xffffffffu, mx0, 1));
            mx0 = fmaxf(mx0, __shfl_xor_sync(0xffffffffu, mx0, 2));
            mx1 = fmaxf(mx1, __shfl_xor_sync(0xffffffffu, mx1, 1));
            mx1 = fmaxf(mx1, __shfl_xor_sync(0xffffffffu, mx1, 2));

            float mn0 = fmaxf(mrun0, mx0), mn1 = fmaxf(mrun1, mx1);
            float corr0 = exp2f(mrun0 - mn0), corr1 = exp2f(mrun1 - mn1);
            mrun0 = mn0; mrun1 = mn1;

#pragma unroll
            for (int nt = 0; nt < 8; nt++) {
                o[nt][0] *= corr0; o[nt][1] *= corr0;
                o[nt][2] *= corr1; o[nt][3] *= corr1;
            }
            osum[0] *= corr0; osum[1] *= corr0;
            osum[2] *= corr1; osum[3] *= corr1;

            // ---- O += P @ V; row sums via all-ones B ----
#pragma unroll
            for (int kcb = 0; kcb < 4; kcb++) {
                uint32_t pa[4];
                pa[0] = ex2_h2(packhf(s[2*kcb][0]   - mn0, s[2*kcb][1]   - mn0));
                pa[1] = ex2_h2(packhf(s[2*kcb][2]   - mn1, s[2*kcb][3]   - mn1));
                pa[2] = ex2_h2(packhf(s[2*kcb+1][0] - mn0, s[2*kcb+1][1] - mn0));
                pa[3] = ex2_h2(packhf(s[2*kcb+1][2] - mn1, s[2*kcb+1][3] - mn1));
                mma_f16(osum, pa, ones2);
#pragma unroll
                for (int db = 0; db < 4; db++) {
                    uint32_t vb[4];
                    uint32_t va = (uint32_t)__cvta_generic_to_shared(
                        &Vs[(kcb * 16 + (lane & 15)) * KP + db * 16 + (lane >> 4) * 8]);
                    LDSM_X4_T(vb[0], vb[1], vb[2], vb[3], va);
                    mma_f16(o[db * 2],     pa, &vb[0]);
                    mma_f16(o[db * 2 + 1], pa, &vb[2]);
                }
            }
        }
    }

    // epilogue: normalize + write fp32 to Y[B,T,C] at head h
    const float inv0 = 1.f / osum[0];
    const float inv1 = 1.f / osum[2];
    const int b = bh >> 4;
    const int h = bh & 15;
    float* y0 = Y + ((size_t)(b * Tt + qr0)) * Cc + h * Dd;
    float* y1 = Y + ((size_t)(b * Tt + qr1)) * Cc + h * Dd;
#pragma unroll
    for (int nt = 0; nt < 8; nt++) {
        int dc = nt * 8 + 2 * c4;
        *(float2*)(y0 + dc) = make_float2(o[nt][0] * inv0, o[nt][1] * inv0);
        *(float2*)(y1 + dc) = make_float2(o[nt][2] * inv1, o[nt][3] * inv1);
    }
}

// ---------------------------------------------------------------------------
// launch
// ---------------------------------------------------------------------------
extern "C" void kernel_launch(void* const* d_in, const int* in_sizes, int n_in,
                              void* d_out, int out_size) {
    const float* x      = (const float*)d_in[0];
    const float* w_attn = (const float*)d_in[1];
    const float* b_attn = (const float*)d_in[2];
    const float* w_proj = (const float*)d_in[3];
    const float* b_proj = (const float*)d_in[4];
    float* out = (float*)d_out;

    uint32_t *qh, *kh, *vh;
    float *y;
    cudaGetSymbolAddress((void**)&qh, g_qh);
    cudaGetSymbolAddress((void**)&kh, g_kh);
    cudaGetSymbolAddress((void**)&vh, g_vh);
    cudaGetSymbolAddress((void**)&y, g_y);

    cudaFuncSetAttribute(flash_f16_kernel,
                         cudaFuncAttributeMaxDynamicSharedMemorySize, FLASH_SMEM);

    // RoPE table
    {
        int total = Tt * (Dd / 2);
        rope_table_kernel<<<(total + 255) / 256, 256>>>();
    }
    // QKV GEMM (tf32 mma.sync) with fused bias + RoPE + fp16 head scatter
    mma_gemm_kernel<<<dim3(N3C / 128, Mrows / 128), 256>>>(
        x, w_attn, b_attn, nullptr, Mrows, N3C, Cc, 1);
    // Flash attention (fp16 mma, work-descending 1D grid)
    flash_f16_kernel<<<(Tt / 128) * Bb * Hh, 256, FLASH_SMEM>>>(qh, kh, vh, y);
    // Output projection (tf32 mma.sync) with fused bias
    mma_gemm_kernel<<<dim3(Cc / 128, Mrows / 128), 256>>>(
        y, w_proj, b_proj, out, Mrows, Cc, Cc, 0);
}

// round 8
// speedup vs baseline: 9.1619x; 1.6108x over previous
#include <cuda_runtime.h>
#include <cuda_fp16.h>
#include <cstdint>

// Problem constants
constexpr int Bb = 2;
constexpr int Tt = 2048;
constexpr int Cc = 1024;
constexpr int Hh = 16;
constexpr int Dd = 64;
constexpr int Mrows = Bb * Tt;        // 4096
constexpr int N3C = 3 * Cc;           // 3072

// Scratch (static device memory)
// fp16 packed (uint32 = 2 halves)
__device__ uint32_t g_xh[Mrows * Cc / 2];      // x in f16
__device__ uint32_t g_wah[Cc * N3C / 2];       // w_attn f16
__device__ uint32_t g_wph[Cc * Cc / 2];        // w_proj f16
__device__ uint32_t g_yh[Mrows * Cc / 2];      // attention out f16
__device__ uint32_t g_qh[Bb * Hh * Tt * 32];   // Q [B,H,T,D/2], scaled log2e/8
__device__ uint32_t g_kh[Bb * Hh * Tt * 32];
__device__ uint32_t g_vh[Bb * Hh * Tt * 32];
__device__ float g_cos[Tt * (Dd / 2)];
__device__ float g_sin[Tt * (Dd / 2)];

__device__ __forceinline__ uint32_t packhf(float lo, float hi) {
    uint32_t r; asm("cvt.rn.f16x2.f32 %0, %1, %2;" : "=r"(r) : "f"(hi), "f"(lo));
    return r;
}
__device__ __forceinline__ uint32_t ex2_h2(uint32_t x) {
    uint32_t r; asm("ex2.approx.f16x2 %0, %1;" : "=r"(r) : "r"(x)); return r;
}
__device__ __forceinline__ void mma_f16(float* c, const uint32_t* a, const uint32_t* b) {
    asm volatile(
        "mma.sync.aligned.m16n8k16.row.col.f32.f16.f16.f32 "
        "{%0,%1,%2,%3}, {%4,%5,%6,%7}, {%8,%9}, {%0,%1,%2,%3};"
        : "+f"(c[0]), "+f"(c[1]), "+f"(c[2]), "+f"(c[3])
        : "r"(a[0]), "r"(a[1]), "r"(a[2]), "r"(a[3]), "r"(b[0]), "r"(b[1]));
}

#define LDSM_X4(r0, r1, r2, r3, addr) \
    asm volatile("ldmatrix.sync.aligned.m8n8.x4.shared.b16 {%0,%1,%2,%3}, [%4];" \
                 : "=r"(r0), "=r"(r1), "=r"(r2), "=r"(r3) : "r"(addr))
#define LDSM_X4_T(r0, r1, r2, r3, addr) \
    asm volatile("ldmatrix.sync.aligned.m8n8.x4.trans.shared.b16 {%0,%1,%2,%3}, [%4];" \
                 : "=r"(r0), "=r"(r1), "=r"(r2), "=r"(r3) : "r"(addr))
#define CP_ASYNC16(dst, src) \
    asm volatile("cp.async.cg.shared.global [%0], [%1], 16;" :: "r"(dst), "l"(src))
#define CP_COMMIT() asm volatile("cp.async.commit_group;" ::: "memory")
#define CP_WAIT(n)  asm volatile("cp.async.wait_group %0;" :: "n"(n) : "memory")

__device__ __forceinline__ uint32_t smaddr(const void* p) {
    return (uint32_t)__cvta_generic_to_shared(p);
}

// ---------------------------------------------------------------------------
// RoPE table + f32->f16 convert
// ---------------------------------------------------------------------------
__global__ void rope_table_kernel() {
    int idx = blockIdx.x * blockDim.x + threadIdx.x;
    if (idx >= Tt * (Dd / 2)) return;
    int t = idx / (Dd / 2);
    int i = idx % (Dd / 2);
    double inv = exp(-((double)(2 * i) / (double)Dd) * log(10000.0));
    float ang = (float)((double)t * inv);
    g_cos[idx] = cosf(ang);
    g_sin[idx] = sinf(ang);
}

__global__ void convert_kernel(const float* __restrict__ in,
                               uint32_t* __restrict__ out, int n2) {
    int i = blockIdx.x * blockDim.x + threadIdx.x;
    if (i >= n2) return;
    float2 v = ((const float2*)in)[i];
    out[i] = packhf(v.x, v.y);
}

// ---------------------------------------------------------------------------
// F16 mma.sync GEMM: out[M,N] = A[M,K] @ B[K,N] + bias[N], fp32 accum.
// CTA 128x128, BK=64, 2-stage cp.async ring, ldmatrix fragments.
// 256 threads = 8 warps (2m x 4n), warp tile 64x32.
// mode 0: fp32 write. mode 1: QKV epilogue (bias + RoPE + fp16 head scatter).
// ---------------------------------------------------------------------------
constexpr int AP2 = 72;    // A smem pitch (halves) = 144 B
constexpr int BP2 = 136;   // B smem pitch (halves) = 272 B
constexpr int HSTAGE = 128 * AP2 + 64 * BP2;        // halves per stage (17920)
constexpr int HGEMM_SMEM = 2 * HSTAGE * 2;          // bytes = 71680

__global__ __launch_bounds__(256, 2) void hgemm_kernel(
    const __half* __restrict__ Ah, const __half* __restrict__ Bh,
    const float* __restrict__ bias, float* __restrict__ out,
    int M, int N, int K, int mode)
{
    extern __shared__ __half sm[];

    const int tid = threadIdx.x;
    const int lane = tid & 31;
    const int wid = tid >> 5;
    const int wm = wid >> 2;        // 0..1
    const int wn = wid & 3;         // 0..3
    const int mBase = blockIdx.y * 128;
    const int nBase = blockIdx.x * 128;
    const int g4 = lane >> 2;
    const int c4 = lane & 3;

    float acc[4][4][4] = {};

    auto prefetch = [&](int it) {
        const int k0 = it * 64;
        __half* As = sm + (it & 1) * HSTAGE;
        __half* Bs = As + 128 * AP2;
#pragma unroll
        for (int p = 0; p < 4; p++) {            // A: 128 rows x 8 chunks
            int id = p * 256 + tid;
            int r = id >> 3, ch = id & 7;
            CP_ASYNC16(smaddr(&As[r * AP2 + ch * 8]),
                       Ah + (size_t)(mBase + r) * K + k0 + ch * 8);
        }
#pragma unroll
        for (int p = 0; p < 4; p++) {            // B: 64 rows x 16 chunks
            int id = p * 256 + tid;
            int r = id >> 4, ch = id & 15;
            CP_ASYNC16(smaddr(&Bs[r * BP2 + ch * 8]),
                       Bh + (size_t)(k0 + r) * N + nBase + ch * 8);
        }
        CP_COMMIT();
    };

    const int KT = K / 64;
    prefetch(0);

    for (int it = 0; it < KT; it++) {
        CP_WAIT(0);
        __syncthreads();
        if (it + 1 < KT) prefetch(it + 1);      // overlaps with compute below

        const __half* As = sm + (it & 1) * HSTAGE;
        const __half* Bs = As + 128 * AP2;

#pragma unroll
        for (int kc = 0; kc < 4; kc++) {
            uint32_t af[4][4];
#pragma unroll
            for (int mt = 0; mt < 4; mt++) {
                uint32_t a = smaddr(&As[(wm * 64 + mt * 16 + (lane & 15)) * AP2 +
                                        kc * 16 + (lane >> 4) * 8]);
                LDSM_X4(af[mt][0], af[mt][1], af[mt][2], af[mt][3], a);
            }
            uint32_t bf[2][4];
#pragma unroll
            for (int nb = 0; nb < 2; nb++) {
                uint32_t a = smaddr(&Bs[(kc * 16 + (lane & 15)) * BP2 +
                                        wn * 32 + nb * 16 + (lane >> 4) * 8]);
                LDSM_X4_T(bf[nb][0], bf[nb][1], bf[nb][2], bf[nb][3], a);
            }
#pragma unroll
            for (int mt = 0; mt < 4; mt++)
#pragma unroll
                for (int nb = 0; nb < 2; nb++) {
                    mma_f16(acc[mt][nb * 2],     af[mt], &bf[nb][0]);
                    mma_f16(acc[mt][nb * 2 + 1], af[mt], &bf[nb][2]);
                }
        }
    }

    // Epilogue
#pragma unroll
    for (int mt = 0; mt < 4; mt++) {
#pragma unroll
        for (int nt = 0; nt < 4; nt++) {
            const int col = nBase + wn * 32 + nt * 8 + 2 * c4;
            const float b0 = __ldg(&bias[col]);
            const float b1 = __ldg(&bias[col + 1]);
            const int row0 = mBase + wm * 64 + mt * 16 + g4;

            float v00 = acc[mt][nt][0] + b0, v01 = acc[mt][nt][1] + b1;
            float v10 = acc[mt][nt][2] + b0, v11 = acc[mt][nt][3] + b1;

            if (mode == 0) {
                *(float2*)(out + (size_t)row0 * N + col) = make_float2(v00, v01);
                *(float2*)(out + (size_t)(row0 + 8) * N + col) = make_float2(v10, v11);
            } else {
                const int part = col >> 10;          // 0=q 1=k 2=v
                const int h = (col & 1023) >> 6;
                const int d = col & 63;
                const int i = d >> 1;
                const int b = row0 >> 11;
                const int t0 = row0 & (Tt - 1);
                const int t1 = (row0 + 8) & (Tt - 1);
                if (part < 2) {
                    float co0 = g_cos[t0 * 32 + i], si0 = g_sin[t0 * 32 + i];
                    float co1 = g_cos[t1 * 32 + i], si1 = g_sin[t1 * 32 + i];
                    float r00 = v00 * co0 - v01 * si0;
                    float r01 = v01 * co0 + v00 * si0;
                    float r10 = v10 * co1 - v11 * si1;
                    float r11 = v11 * co1 + v10 * si1;
                    v00 = r00; v01 = r01; v10 = r10; v11 = r11;
                }
                if (part == 0) {   // fold log2(e)/sqrt(D) into Q (exp2 domain)
                    const float qs = 0.18033688011111366f;
                    v00 *= qs; v01 *= qs; v10 *= qs; v11 *= qs;
                }
                uint32_t* dst = (part == 0) ? g_qh : (part == 1) ? g_kh : g_vh;
                size_t base = ((size_t)(b * Hh + h)) * Tt;
                dst[(base + t0) * 32 + (d >> 1)] = packhf(v00, v01);
                dst[(base + t1) * 32 + (d >> 1)] = packhf(v10, v11);
            }
        }
    }
}

// ---------------------------------------------------------------------------
// Flash attention (causal), fp16 mma + ldmatrix (R7 design, verified).
// Now writes attention output in fp16 (packed) for the f16 projection GEMM.
// ---------------------------------------------------------------------------
constexpr int KP = 72;
constexpr int STAGE_H = 2 * 64 * KP;
constexpr int FLASH_SMEM = 3 * STAGE_H * 2;

__global__ __launch_bounds__(256) void flash_f16_kernel(
    const uint32_t* __restrict__ Qh, const uint32_t* __restrict__ Kh,
    const uint32_t* __restrict__ Vh, uint32_t* __restrict__ Yh)
{
    extern __shared__ __half smf[];

    const int tid = threadIdx.x;
    const int lane = tid & 31;
    const int w = tid >> 5;
    const int g4 = lane >> 2;
    const int c4 = lane & 3;

    const int cta = blockIdx.x;
    const int bh = cta & 31;
    const int qb = (Tt / 128 - 1) - (cta >> 5);
    const int m0 = qb << 7;

    const int wRow0 = m0 + w * 16;
    const int qr0 = wRow0 + g4;
    const int qr1 = qr0 + 8;

    const uint32_t* Qb = Qh + (size_t)bh * Tt * 32;
    const uint32_t* Kb = Kh + (size_t)bh * Tt * 32;
    const uint32_t* Vb = Vh + (size_t)bh * Tt * 32;

    uint32_t qf[4][4];
    {
        const uint32_t* q0 = Qb + (size_t)qr0 * 32;
        const uint32_t* q1 = Qb + (size_t)qr1 * 32;
#pragma unroll
        for (int kc = 0; kc < 4; kc++) {
            qf[kc][0] = q0[kc * 8 + c4];
            qf[kc][1] = q1[kc * 8 + c4];
            qf[kc][2] = q0[kc * 8 + c4 + 4];
            qf[kc][3] = q1[kc * 8 + c4 + 4];
        }
    }

    float o[8][4] = {};
    float osum[4] = {};
    float mrun0 = -1e30f, mrun1 = -1e30f;

    const int ntiles = (m0 + 128) / 64;
    const uint32_t ones2[2] = {0x3C003C00u, 0x3C003C00u};

    auto prefetch = [&](int it) {
        const int j0 = it * 64;
        __half* Ks = smf + (it % 3) * STAGE_H;
        __half* Vs = Ks + 64 * KP;
#pragma unroll
        for (int p = 0; p < 2; p++) {
            int id = p * 256 + tid;
            int r = id >> 3, ch = id & 7;
            uint32_t kd = smaddr(&Ks[r * KP + ch * 8]);
            uint32_t vd = smaddr(&Vs[r * KP + ch * 8]);
            const char* ksrc = (const char*)(Kb + (size_t)(j0 + r) * 32 + ch * 4);
            const char* vsrc = (const char*)(Vb + (size_t)(j0 + r) * 32 + ch * 4);
            CP_ASYNC16(kd, ksrc);
            CP_ASYNC16(vd, vsrc);
        }
        CP_COMMIT();
    };

    prefetch(0);
    if (1 < ntiles) prefetch(1); else CP_COMMIT();

    for (int it = 0; it < ntiles; it++) {
        const int j0 = it * 64;
        __half* Ks = smf + (it % 3) * STAGE_H;
        __half* Vs = Ks + 64 * KP;

        CP_WAIT(1);
        __syncthreads();
        if (it + 2 < ntiles) prefetch(it + 2);

        if (j0 <= wRow0 + 15) {
            float s[8][4] = {};
#pragma unroll
            for (int nt = 0; nt < 8; nt++) {
                uint32_t kb[8];
                uint32_t a0 = smaddr(&Ks[(nt * 8 + (lane & 7)) * KP + ((lane >> 3) & 3) * 8]);
                LDSM_X4(kb[0], kb[1], kb[2], kb[3], a0);
                uint32_t a1 = smaddr(&Ks[(nt * 8 + (lane & 7)) * KP + 32 + ((lane >> 3) & 3) * 8]);
                LDSM_X4(kb[4], kb[5], kb[6], kb[7], a1);
#pragma unroll
                for (int kc = 0; kc < 4; kc++)
                    mma_f16(s[nt], qf[kc], &kb[kc * 2]);
            }

            if (j0 + 63 > wRow0) {
#pragma unroll
                for (int nt = 0; nt < 8; nt++) {
                    int cb = j0 + nt * 8 + 2 * c4;
                    if (cb > qr0)     s[nt][0] = -1e30f;
                    if (cb + 1 > qr0) s[nt][1] = -1e30f;
                    if (cb > qr1)     s[nt][2] = -1e30f;
                    if (cb + 1 > qr1) s[nt][3] = -1e30f;
                }
            }

            float mx0 = -1e30f, mx1 = -1e30f;
#pragma unroll
            for (int nt = 0; nt < 8; nt++) {
                mx0 = fmaxf(mx0, fmaxf(s[nt][0], s[nt][1]));
                mx1 = fmaxf(mx1, fmaxf(s[nt][2], s[nt][3]));
            }
            mx0 = fmaxf(mx0, __shfl_xor_sync(0xffffffffu, mx0, 1));
            mx0 = fmaxf(mx0, __shfl_xor_sync(0xffffffffu, mx0, 2));
            mx1 = fmaxf(mx1, __shfl_xor_sync(0xffffffffu, mx1, 1));
            mx1 = fmaxf(mx1, __shfl_xor_sync(0xffffffffu, mx1, 2));

            float mn0 = fmaxf(mrun0, mx0), mn1 = fmaxf(mrun1, mx1);
            float corr0 = exp2f(mrun0 - mn0), corr1 = exp2f(mrun1 - mn1);
            mrun0 = mn0; mrun1 = mn1;

#pragma unroll
            for (int nt = 0; nt < 8; nt++) {
                o[nt][0] *= corr0; o[nt][1] *= corr0;
                o[nt][2] *= corr1; o[nt][3] *= corr1;
            }
            osum[0] *= corr0; osum[1] *= corr0;
            osum[2] *= corr1; osum[3] *= corr1;

#pragma unroll
            for (int kcb = 0; kcb < 4; kcb++) {
                uint32_t pa[4];
                pa[0] = ex2_h2(packhf(s[2*kcb][0]   - mn0, s[2*kcb][1]   - mn0));
                pa[1] = ex2_h2(packhf(s[2*kcb][2]   - mn1, s[2*kcb][3]   - mn1));
                pa[2] = ex2_h2(packhf(s[2*kcb+1][0] - mn0, s[2*kcb+1][1] - mn0));
                pa[3] = ex2_h2(packhf(s[2*kcb+1][2] - mn1, s[2*kcb+1][3] - mn1));
                mma_f16(osum, pa, ones2);
#pragma unroll
                for (int db = 0; db < 4; db++) {
                    uint32_t vb[4];
                    uint32_t va = smaddr(&Vs[(kcb * 16 + (lane & 15)) * KP +
                                             db * 16 + (lane >> 4) * 8]);
                    LDSM_X4_T(vb[0], vb[1], vb[2], vb[3], va);
                    mma_f16(o[db * 2],     pa, &vb[0]);
                    mma_f16(o[db * 2 + 1], pa, &vb[2]);
                }
            }
        }
    }

    // epilogue: normalize + write fp16 packed to Yh [B*T, C/2]
    const float inv0 = 1.f / osum[0];
    const float inv1 = 1.f / osum[2];
    const int b = bh >> 4;
    const int h = bh & 15;
    uint32_t* y0 = Yh + ((size_t)(b * Tt + qr0)) * (Cc / 2) + h * 32;
    uint32_t* y1 = Yh + ((size_t)(b * Tt + qr1)) * (Cc / 2) + h * 32;
#pragma unroll
    for (int nt = 0; nt < 8; nt++) {
        int dw = (nt * 8 + 2 * c4) >> 1;
        y0[dw] = packhf(o[nt][0] * inv0, o[nt][1] * inv0);
        y1[dw] = packhf(o[nt][2] * inv1, o[nt][3] * inv1);
    }
}

// ---------------------------------------------------------------------------
// launch
// ---------------------------------------------------------------------------
extern "C" void kernel_launch(void* const* d_in, const int* in_sizes, int n_in,
                              void* d_out, int out_size) {
    const float* x      = (const float*)d_in[0];
    const float* w_attn = (const float*)d_in[1];
    const float* b_attn = (const float*)d_in[2];
    const float* w_proj = (const float*)d_in[3];
    const float* b_proj = (const float*)d_in[4];
    float* out = (float*)d_out;

    uint32_t *xh, *wah, *wph, *yh, *qh, *kh, *vh;
    cudaGetSymbolAddress((void**)&xh, g_xh);
    cudaGetSymbolAddress((void**)&wah, g_wah);
    cudaGetSymbolAddress((void**)&wph, g_wph);
    cudaGetSymbolAddress((void**)&yh, g_yh);
    cudaGetSymbolAddress((void**)&qh, g_qh);
    cudaGetSymbolAddress((void**)&kh, g_kh);
    cudaGetSymbolAddress((void**)&vh, g_vh);

    cudaFuncSetAttribute(flash_f16_kernel,
                         cudaFuncAttributeMaxDynamicSharedMemorySize, FLASH_SMEM);
    cudaFuncSetAttribute(hgemm_kernel,
                         cudaFuncAttributeMaxDynamicSharedMemorySize, HGEMM_SMEM);

    // RoPE table + f16 conversions
    {
        int total = Tt * (Dd / 2);
        rope_table_kernel<<<(total + 255) / 256, 256>>>();
    }
    convert_kernel<<<(Mrows * Cc / 2 + 255) / 256, 256>>>(x, xh, Mrows * Cc / 2);
    convert_kernel<<<(Cc * N3C / 2 + 255) / 256, 256>>>(w_attn, wah, Cc * N3C / 2);
    convert_kernel<<<(Cc * Cc / 2 + 255) / 256, 256>>>(w_proj, wph, Cc * Cc / 2);

    // QKV GEMM (f16 mma) with fused bias + RoPE + fp16 head scatter
    hgemm_kernel<<<dim3(N3C / 128, Mrows / 128), 256, HGEMM_SMEM>>>(
        (const __half*)xh, (const __half*)wah, b_attn, nullptr, Mrows, N3C, Cc, 1);
    // Flash attention (fp16 mma)
    flash_f16_kernel<<<(Tt / 128) * Bb * Hh, 256, FLASH_SMEM>>>(qh, kh, vh, yh);
    // Output projection (f16 mma) with fused bias, fp32 out
    hgemm_kernel<<<dim3(Cc / 128, Mrows / 128), 256, HGEMM_SMEM>>>(
        (const __half*)yh, (const __half*)wph, b_proj, out, Mrows, Cc, Cc, 0);
}